// round 2
// baseline (speedup 1.0000x reference)
#include <cuda_runtime.h>
#include <math.h>

// Problem constants
#define Bb   4
#define Nseq 512
#define Dd   1024
#define Hh   16
#define HDd  64
#define HIDd 4096
#define MM   (Bb * Nseq)     // 2048 rows
#define MODS (6 * Dd)        // 6144

// ---- scratch (no allocs allowed -> __device__ globals) ----
__device__ float g_mod[Bb * MODS];                        // adaLN modulation
__device__ float g_xn[MM * Dd];                           // normalized/modulated activations
__device__ float g_qkv[MM * 3 * Dd];                      // qkv projections
__device__ float g_bias[(size_t)Bb * Hh * Nseq * Nseq];   // rel-pos bias [B,H,N,N] (mask folded in)
__device__ float g_scores[(size_t)Bb * Hh * Nseq * Nseq]; // attention scores / probs
__device__ float g_attn[MM * Dd];                         // attention output (pre-proj)
__device__ float g_x1[MM * Dd];                           // x after attention residual
__device__ float g_hbuf[(size_t)MM * HIDd];               // MLP hidden

// ============================================================
// 1) adaLN: mod = silu(t_emb) @ w_ada^T + b_ada   [B, 6144]
//    One warp per output element; silu(t) staged in smem.
// ============================================================
__global__ void adaln_k(const float* __restrict__ t_emb,
                        const float* __restrict__ w,
                        const float* __restrict__ bias) {
    __shared__ float st[Dd];
    int b = blockIdx.y;
    for (int i = threadIdx.x; i < Dd; i += 256) {
        float t = t_emb[b * Dd + i];
        st[i] = t / (1.0f + expf(-t));
    }
    __syncthreads();
    int warp = threadIdx.x >> 5, lane = threadIdx.x & 31;
    int o = blockIdx.x * 8 + warp;              // grid.x = 768 -> 6144 outputs
    const float* wr = w + (size_t)o * Dd;
    float acc = 0.0f;
    for (int k = lane; k < Dd; k += 32) acc = fmaf(st[k], wr[k], acc);
    #pragma unroll
    for (int s = 16; s; s >>= 1) acc += __shfl_xor_sync(0xffffffff, acc, s);
    if (lane == 0) g_mod[b * MODS + o] = acc + bias[o];
}

// ============================================================
// 2) LayerNorm + adaLN modulate: one block per row
// ============================================================
__global__ void ln_mod_k(const float* __restrict__ x,
                         const float* __restrict__ g,
                         const float* __restrict__ beta,
                         int shiftOff, int scaleOff,
                         float* __restrict__ out) {
    int row = blockIdx.x;
    int b = row >> 9;  // 512 rows per batch
    const float* xr = x + (size_t)row * Dd;
    __shared__ float r1[256], r2[256];
    float s = 0.0f, s2 = 0.0f;
    for (int j = threadIdx.x; j < Dd; j += 256) {
        float v = xr[j];
        s += v; s2 = fmaf(v, v, s2);
    }
    r1[threadIdx.x] = s; r2[threadIdx.x] = s2;
    __syncthreads();
    for (int st = 128; st; st >>= 1) {
        if (threadIdx.x < st) {
            r1[threadIdx.x] += r1[threadIdx.x + st];
            r2[threadIdx.x] += r2[threadIdx.x + st];
        }
        __syncthreads();
    }
    float mu = r1[0] * (1.0f / Dd);
    float var = r2[0] * (1.0f / Dd) - mu * mu;
    float rstd = rsqrtf(var + 1e-5f);
    const float* sh = g_mod + b * MODS + shiftOff;
    const float* sc = g_mod + b * MODS + scaleOff;
    float* orow = out + (size_t)row * Dd;
    for (int j = threadIdx.x; j < Dd; j += 256) {
        float v = (xr[j] - mu) * rstd * g[j] + beta[j];
        orow[j] = fmaf(v, 1.0f + sc[j], sh[j]);
    }
}

// ============================================================
// 3) Generic NT SGEMM: C[M,N] = A[M,K] @ B[N,K]^T + bias
//    128x128x16 tiles, 256 threads, 8x8 microtile per thread.
//    All shapes are multiples of 128/16 -> no guards.
//    EPI: 0 plain, 1 exact GELU, 2 residual + per-(batch,col) gate
// ============================================================
template <int EPI>
__global__ void __launch_bounds__(256, 2)
sgemm_nt(const float* __restrict__ A, const float* __restrict__ Bm,
         const float* __restrict__ bias, const float* __restrict__ res,
         const float* __restrict__ gate, float* __restrict__ C,
         int M, int N, int K) {
    __shared__ float As[16][132];
    __shared__ float Bs[16][132];
    int bm = blockIdx.y * 128, bn = blockIdx.x * 128;
    int tid = threadIdx.x;
    int lr = tid >> 1;            // 0..127 tile row
    int lc = (tid & 1) * 8;       // k offset 0 or 8
    int tx = tid & 15, ty = tid >> 4;
    float acc[8][8] = {};
    const float* Aptr = A + (size_t)(bm + lr) * K + lc;
    const float* Bptr = Bm + (size_t)(bn + lr) * K + lc;
    for (int k0 = 0; k0 < K; k0 += 16) {
        float4 a0 = *(const float4*)(Aptr + k0);
        float4 a1 = *(const float4*)(Aptr + k0 + 4);
        float4 b0 = *(const float4*)(Bptr + k0);
        float4 b1 = *(const float4*)(Bptr + k0 + 4);
        __syncthreads();
        As[lc + 0][lr] = a0.x; As[lc + 1][lr] = a0.y; As[lc + 2][lr] = a0.z; As[lc + 3][lr] = a0.w;
        As[lc + 4][lr] = a1.x; As[lc + 5][lr] = a1.y; As[lc + 6][lr] = a1.z; As[lc + 7][lr] = a1.w;
        Bs[lc + 0][lr] = b0.x; Bs[lc + 1][lr] = b0.y; Bs[lc + 2][lr] = b0.z; Bs[lc + 3][lr] = b0.w;
        Bs[lc + 4][lr] = b1.x; Bs[lc + 5][lr] = b1.y; Bs[lc + 6][lr] = b1.z; Bs[lc + 7][lr] = b1.w;
        __syncthreads();
        #pragma unroll
        for (int k = 0; k < 16; k++) {
            float ar[8], br[8];
            #pragma unroll
            for (int i = 0; i < 8; i++) ar[i] = As[k][ty * 8 + i];
            #pragma unroll
            for (int j = 0; j < 8; j++) br[j] = Bs[k][tx * 8 + j];
            #pragma unroll
            for (int i = 0; i < 8; i++)
                #pragma unroll
                for (int j = 0; j < 8; j++)
                    acc[i][j] = fmaf(ar[i], br[j], acc[i][j]);
        }
    }
    #pragma unroll
    for (int i = 0; i < 8; i++) {
        int r = bm + ty * 8 + i;
        int bb = r >> 9;
        size_t rowoff = (size_t)r * N + bn + tx * 8;
        #pragma unroll
        for (int j = 0; j < 8; j++) {
            int c = bn + tx * 8 + j;
            float v = acc[i][j] + bias[c];
            if (EPI == 1) v = v * normcdff(v);                       // exact GELU
            if (EPI == 2) v = res[rowoff + j] + gate[bb * MODS + c] * v;
            C[rowoff + j] = v;
        }
    }
}

// ============================================================
// 4) Rel-pos bias MLP: (2 -> 64 relu -> 16) per (b,n,m),
//    written transposed to [B,H,N,N]; key mask folded as -inf.
// ============================================================
__global__ void relpos_k(const float* __restrict__ rel,
                         const float* __restrict__ w1, const float* __restrict__ b1,
                         const float* __restrict__ w2, const float* __restrict__ b2,
                         const int* __restrict__ mask) {
    __shared__ float W1[128], B1[64], W2[16 * 64], B2[16];
    int tid = threadIdx.x;
    if (tid < 128) W1[tid] = w1[tid];
    if (tid < 64)  B1[tid] = b1[tid];
    for (int i = tid; i < 1024; i += 256) W2[i] = w2[i];
    if (tid < 16)  B2[tid] = b2[tid];
    __syncthreads();
    int b = blockIdx.z, n = blockIdx.y, m = blockIdx.x * 256 + tid;
    float2 r = *(const float2*)(rel + ((size_t)((b * Nseq + n) * Nseq + m)) * 2);
    bool ok = (mask[b * Nseq + m] != 0);
    float out[16];
    #pragma unroll
    for (int t = 0; t < 16; t++) out[t] = B2[t];
    #pragma unroll 16
    for (int j = 0; j < 64; j++) {
        float hj = fmaxf(fmaf(W1[2 * j], r.x, fmaf(W1[2 * j + 1], r.y, B1[j])), 0.0f);
        #pragma unroll
        for (int t = 0; t < 16; t++) out[t] = fmaf(W2[t * 64 + j], hj, out[t]);
    }
    #pragma unroll
    for (int t = 0; t < 16; t++) {
        size_t idx = (((size_t)(b * Hh + t) * Nseq) + n) * Nseq + m;
        g_bias[idx] = ok ? out[t] : -INFINITY;
    }
}

// ============================================================
// 5) Attention scores: S[b,h,n,m] = 0.125 * q.k + bias
//    64x64 tile per block, full HD=64 in one pass.
// ============================================================
__global__ void scores_k() {
    __shared__ float Qs[64][65], Ks[64][65];
    int bh = blockIdx.z, b = bh >> 4, h = bh & 15;
    int n0 = blockIdx.y * 64, m0 = blockIdx.x * 64;
    int tid = threadIdx.x;
    int lrow = tid >> 2, lcol = (tid & 3) * 16;
    const float* qb = g_qkv + (size_t)(b * Nseq + n0 + lrow) * 3072 + h * 64 + lcol;
    const float* kb = g_qkv + (size_t)(b * Nseq + m0 + lrow) * 3072 + 1024 + h * 64 + lcol;
    #pragma unroll
    for (int q = 0; q < 4; q++) {
        float4 v = ((const float4*)qb)[q];
        Qs[lrow][lcol + q * 4 + 0] = v.x; Qs[lrow][lcol + q * 4 + 1] = v.y;
        Qs[lrow][lcol + q * 4 + 2] = v.z; Qs[lrow][lcol + q * 4 + 3] = v.w;
        float4 w = ((const float4*)kb)[q];
        Ks[lrow][lcol + q * 4 + 0] = w.x; Ks[lrow][lcol + q * 4 + 1] = w.y;
        Ks[lrow][lcol + q * 4 + 2] = w.z; Ks[lrow][lcol + q * 4 + 3] = w.w;
    }
    __syncthreads();
    int tx = tid & 15, ty = tid >> 4;
    float acc[4][4] = {};
    #pragma unroll 8
    for (int k = 0; k < 64; k++) {
        float ar[4], br[4];
        #pragma unroll
        for (int i = 0; i < 4; i++) ar[i] = Qs[ty * 4 + i][k];
        #pragma unroll
        for (int j = 0; j < 4; j++) br[j] = Ks[tx * 4 + j][k];
        #pragma unroll
        for (int i = 0; i < 4; i++)
            #pragma unroll
            for (int j = 0; j < 4; j++)
                acc[i][j] = fmaf(ar[i], br[j], acc[i][j]);
    }
    #pragma unroll
    for (int i = 0; i < 4; i++) {
        int n = n0 + ty * 4 + i;
        #pragma unroll
        for (int j = 0; j < 4; j++) {
            int m = m0 + tx * 4 + j;
            size_t idx = ((size_t)bh * Nseq + n) * Nseq + m;
            g_scores[idx] = fmaf(acc[i][j], 0.125f, g_bias[idx]);
        }
    }
}

// ============================================================
// 6) Row softmax over m (512), one warp per row
// ============================================================
__global__ void softmax_k() {
    int row = blockIdx.x * 8 + (threadIdx.x >> 5);
    int lane = threadIdx.x & 31;
    float* p = g_scores + (size_t)row * Nseq;
    float vals[16];
    float mx = -INFINITY;
    #pragma unroll
    for (int i = 0; i < 16; i++) { vals[i] = p[lane + i * 32]; mx = fmaxf(mx, vals[i]); }
    #pragma unroll
    for (int s = 16; s; s >>= 1) mx = fmaxf(mx, __shfl_xor_sync(0xffffffff, mx, s));
    float sum = 0.0f;
    #pragma unroll
    for (int i = 0; i < 16; i++) { vals[i] = __expf(vals[i] - mx); sum += vals[i]; }
    #pragma unroll
    for (int s = 16; s; s >>= 1) sum += __shfl_xor_sync(0xffffffff, sum, s);
    float inv = 1.0f / sum;
    #pragma unroll
    for (int i = 0; i < 16; i++) p[lane + i * 32] = vals[i] * inv;
}

// ============================================================
// 7) P @ V : out[b,n,h,d], 64-row tile per block over all m
// ============================================================
__global__ void pv_k() {
    __shared__ float Ps[64][65], Vs[64][65];
    int bh = blockIdx.y, b = bh >> 4, h = bh & 15;
    int n0 = blockIdx.x * 64;
    int tid = threadIdx.x;
    int lrow = tid >> 2, lcol = (tid & 3) * 16;
    int tx = tid & 15, ty = tid >> 4;
    float acc[4][4] = {};
    for (int m0 = 0; m0 < Nseq; m0 += 64) {
        const float* pb = g_scores + ((size_t)bh * Nseq + n0 + lrow) * Nseq + m0 + lcol;
        const float* vb = g_qkv + (size_t)(b * Nseq + m0 + lrow) * 3072 + 2048 + h * 64 + lcol;
        __syncthreads();
        #pragma unroll
        for (int q = 0; q < 4; q++) {
            float4 v = ((const float4*)pb)[q];
            Ps[lrow][lcol + q * 4 + 0] = v.x; Ps[lrow][lcol + q * 4 + 1] = v.y;
            Ps[lrow][lcol + q * 4 + 2] = v.z; Ps[lrow][lcol + q * 4 + 3] = v.w;
            float4 w = ((const float4*)vb)[q];
            Vs[lrow][lcol + q * 4 + 0] = w.x; Vs[lrow][lcol + q * 4 + 1] = w.y;
            Vs[lrow][lcol + q * 4 + 2] = w.z; Vs[lrow][lcol + q * 4 + 3] = w.w;
        }
        __syncthreads();
        #pragma unroll 8
        for (int k = 0; k < 64; k++) {
            float ar[4], br[4];
            #pragma unroll
            for (int i = 0; i < 4; i++) ar[i] = Ps[ty * 4 + i][k];
            #pragma unroll
            for (int j = 0; j < 4; j++) br[j] = Vs[k][tx * 4 + j];
            #pragma unroll
            for (int i = 0; i < 4; i++)
                #pragma unroll
                for (int j = 0; j < 4; j++)
                    acc[i][j] = fmaf(ar[i], br[j], acc[i][j]);
        }
    }
    #pragma unroll
    for (int i = 0; i < 4; i++) {
        int n = n0 + ty * 4 + i;
        #pragma unroll
        for (int j = 0; j < 4; j++) {
            g_attn[(size_t)(b * Nseq + n) * Dd + h * 64 + tx * 4 + j] = acc[i][j];
        }
    }
}

// ============================================================
// host-side launcher
// ============================================================
extern "C" void kernel_launch(void* const* d_in, const int* in_sizes, int n_in,
                              void* d_out, int out_size) {
    const float* x      = (const float*)d_in[0];
    const float* t_emb  = (const float*)d_in[1];
    const float* rel    = (const float*)d_in[2];
    const int*   mask   = (const int*)d_in[3];
    const float* w_ada  = (const float*)d_in[4];
    const float* b_ada  = (const float*)d_in[5];
    const float* g1     = (const float*)d_in[6];
    const float* beta1  = (const float*)d_in[7];
    const float* g2     = (const float*)d_in[8];
    const float* beta2  = (const float*)d_in[9];
    const float* w_qkv  = (const float*)d_in[10];
    const float* b_qkv  = (const float*)d_in[11];
    const float* w_proj = (const float*)d_in[12];
    const float* b_proj = (const float*)d_in[13];
    const float* w_rp1  = (const float*)d_in[14];
    const float* b_rp1  = (const float*)d_in[15];
    const float* w_rp2  = (const float*)d_in[16];
    const float* b_rp2  = (const float*)d_in[17];
    const float* w_fc1  = (const float*)d_in[18];
    const float* b_fc1  = (const float*)d_in[19];
    const float* w_fc2  = (const float*)d_in[20];
    const float* b_fc2  = (const float*)d_in[21];
    float* out = (float*)d_out;

    void *p_mod, *p_xn, *p_qkv, *p_attn, *p_x1, *p_h;
    cudaGetSymbolAddress(&p_mod,  g_mod);
    cudaGetSymbolAddress(&p_xn,   g_xn);
    cudaGetSymbolAddress(&p_qkv,  g_qkv);
    cudaGetSymbolAddress(&p_attn, g_attn);
    cudaGetSymbolAddress(&p_x1,   g_x1);
    cudaGetSymbolAddress(&p_h,    g_hbuf);
    float* modf = (float*)p_mod;

    // 1. adaLN modulation
    adaln_k<<<dim3(768, 4), 256>>>(t_emb, w_ada, b_ada);
    // 2. LN1 + modulate (shift_s @ 0, scale_s @ D)
    ln_mod_k<<<MM, 256>>>(x, g1, beta1, 0, Dd, (float*)p_xn);
    // 3. QKV projection: [2048,1024] x [3072,1024]^T
    sgemm_nt<0><<<dim3(3072 / 128, MM / 128), 256>>>(
        (const float*)p_xn, w_qkv, b_qkv, nullptr, nullptr, (float*)p_qkv, MM, 3072, Dd);
    // 4. rel-pos bias (+key mask folded in)
    relpos_k<<<dim3(2, Nseq, Bb), 256>>>(rel, w_rp1, b_rp1, w_rp2, b_rp2, mask);
    // 5. scores
    scores_k<<<dim3(8, 8, Bb * Hh), 256>>>();
    // 6. softmax
    softmax_k<<<(Bb * Hh * Nseq) / 8, 256>>>();
    // 7. P @ V
    pv_k<<<dim3(8, Bb * Hh), 256>>>();
    // 8. proj + residual with gate_s (chunk 2)
    sgemm_nt<2><<<dim3(1024 / 128, MM / 128), 256>>>(
        (const float*)p_attn, w_proj, b_proj, x, modf + 2 * Dd, (float*)p_x1, MM, Dd, Dd);
    // 9. LN2 + modulate (shift_m @ 3D, scale_m @ 4D)
    ln_mod_k<<<MM, 256>>>((const float*)p_x1, g2, beta2, 3 * Dd, 4 * Dd, (float*)p_xn);
    // 10. fc1 + exact GELU
    sgemm_nt<1><<<dim3(HIDd / 128, MM / 128), 256>>>(
        (const float*)p_xn, w_fc1, b_fc1, nullptr, nullptr, (float*)p_h, MM, HIDd, Dd);
    // 11. fc2 + residual with gate_m (chunk 5) -> final output
    sgemm_nt<2><<<dim3(1024 / 128, MM / 128), 256>>>(
        (const float*)p_h, w_fc2, b_fc2, (const float*)p_x1, modf + 5 * Dd, out, MM, Dd, HIDd);
}

// round 5
// speedup vs baseline: 1.7493x; 1.7493x over previous
#include <cuda_runtime.h>
#include <cuda_bf16.h>
#include <stdint.h>
#include <math.h>

// Problem constants
#define Bb   4
#define Nseq 512
#define Dd   1024
#define Hh   16
#define HDd  64
#define HIDd 4096
#define MM   (Bb * Nseq)     // 2048 rows
#define MODS (6 * Dd)        // 6144

// ---- scratch (no allocs allowed -> __device__ globals) ----
__device__ float g_mod[Bb * MODS];
__device__ float g_xn[MM * Dd];
__device__ float g_qkv[MM * 3 * Dd];
__device__ float g_bias[(size_t)Bb * Hh * Nseq * Nseq];
__device__ float g_scores[(size_t)Bb * Hh * Nseq * Nseq];
__device__ float g_attn[MM * Dd];
__device__ float g_x1[MM * Dd];
__device__ float g_hbuf[(size_t)MM * HIDd];

// ============================================================
// 1) adaLN: mod = silu(t_emb) @ w_ada^T + b_ada   [B, 6144]
// ============================================================
__global__ void adaln_k(const float* __restrict__ t_emb,
                        const float* __restrict__ w,
                        const float* __restrict__ bias) {
    __shared__ float st[Dd];
    int b = blockIdx.y;
    for (int i = threadIdx.x; i < Dd; i += 256) {
        float t = t_emb[b * Dd + i];
        st[i] = t / (1.0f + expf(-t));
    }
    __syncthreads();
    int warp = threadIdx.x >> 5, lane = threadIdx.x & 31;
    int o = blockIdx.x * 8 + warp;
    const float* wr = w + (size_t)o * Dd;
    float acc = 0.0f;
    for (int k = lane; k < Dd; k += 32) acc = fmaf(st[k], wr[k], acc);
    #pragma unroll
    for (int s = 16; s; s >>= 1) acc += __shfl_xor_sync(0xffffffff, acc, s);
    if (lane == 0) g_mod[b * MODS + o] = acc + bias[o];
}

// ============================================================
// 2) LayerNorm + adaLN modulate: one block per row
// ============================================================
__global__ void ln_mod_k(const float* __restrict__ x,
                         const float* __restrict__ g,
                         const float* __restrict__ beta,
                         int shiftOff, int scaleOff,
                         float* __restrict__ out) {
    int row = blockIdx.x;
    int b = row >> 9;
    const float* xr = x + (size_t)row * Dd;
    __shared__ float r1[256], r2[256];
    float s = 0.0f, s2 = 0.0f;
    for (int j = threadIdx.x; j < Dd; j += 256) {
        float v = xr[j];
        s += v; s2 = fmaf(v, v, s2);
    }
    r1[threadIdx.x] = s; r2[threadIdx.x] = s2;
    __syncthreads();
    for (int st = 128; st; st >>= 1) {
        if (threadIdx.x < st) {
            r1[threadIdx.x] += r1[threadIdx.x + st];
            r2[threadIdx.x] += r2[threadIdx.x + st];
        }
        __syncthreads();
    }
    float mu = r1[0] * (1.0f / Dd);
    float var = r2[0] * (1.0f / Dd) - mu * mu;
    float rstd = rsqrtf(var + 1e-5f);
    const float* sh = g_mod + b * MODS + shiftOff;
    const float* sc = g_mod + b * MODS + scaleOff;
    float* orow = out + (size_t)row * Dd;
    for (int j = threadIdx.x; j < Dd; j += 256) {
        float v = (xr[j] - mu) * rstd * g[j] + beta[j];
        orow[j] = fmaf(v, 1.0f + sc[j], sh[j]);
    }
}

// ============================================================
// 3) Tensor-core NT GEMM with bf16 hi/lo split (3-MMA trick)
//    C[M,N] = A[M,K] @ B[N,K]^T + bias, fp32-level accuracy.
//    Block 128x128x32, 8 warps, warp tile 64x32 (m16n8k16 MMAs).
//    EPI: 0 plain, 1 exact GELU, 2 residual + per-(batch,col) gate
// ============================================================
#define KC 32          // k-chunk
#define SPITCH 40      // smem row pitch in bf16 elems (80B: conflict-free ldS)

__device__ __forceinline__ uint32_t pack_bf2(__nv_bfloat16 a, __nv_bfloat16 b) {
    unsigned short ua = *(unsigned short*)&a;
    unsigned short ub = *(unsigned short*)&b;
    return ((uint32_t)ub << 16) | ua;
}

__device__ __forceinline__ void mma_bf16(float* c, const uint32_t* a, const uint32_t* b) {
    asm volatile(
        "mma.sync.aligned.m16n8k16.row.col.f32.bf16.bf16.f32 "
        "{%0,%1,%2,%3}, {%4,%5,%6,%7}, {%8,%9}, {%0,%1,%2,%3};"
        : "+f"(c[0]), "+f"(c[1]), "+f"(c[2]), "+f"(c[3])
        : "r"(a[0]), "r"(a[1]), "r"(a[2]), "r"(a[3]), "r"(b[0]), "r"(b[1]));
}

template <int EPI>
__global__ void __launch_bounds__(256, 2)
gemm_tc(const float* __restrict__ A, const float* __restrict__ Bm,
        const float* __restrict__ bias, const float* __restrict__ res,
        const float* __restrict__ gate, float* __restrict__ C,
        int M, int N, int K) {
    __shared__ __nv_bfloat16 AsH[128][SPITCH], AsL[128][SPITCH];
    __shared__ __nv_bfloat16 BsH[128][SPITCH], BsL[128][SPITCH];

    int bm = blockIdx.y * 128, bn = blockIdx.x * 128;
    int tid = threadIdx.x;
    int warp = tid >> 5, lane = tid & 31;
    int wm = warp >> 2, wn = warp & 3;   // 2 x 4 warp grid, warp tile 64x32
    int g = lane >> 2, tig = lane & 3;   // mma fragment coords

    int lr  = tid >> 1;                  // 0..127 tile row for staging
    int kof = (tid & 1) * 16;            // 16 floats per thread per row

    float acc[4][4][4] = {};             // [m-tile][n-tile][c-regs]

    const float* Aptr = A + (size_t)(bm + lr) * K + kof;
    const float* Bptr = Bm + (size_t)(bn + lr) * K + kof;

    for (int k0 = 0; k0 < K; k0 += KC) {
        // ---- stage + split to bf16 hi/lo planes ----
        float4 fa[4], fb[4];
        #pragma unroll
        for (int q = 0; q < 4; q++) {
            fa[q] = *(const float4*)(Aptr + k0 + q * 4);
            fb[q] = *(const float4*)(Bptr + k0 + q * 4);
        }
        __syncthreads();
        {
            uint32_t* aH = (uint32_t*)&AsH[lr][kof];
            uint32_t* aL = (uint32_t*)&AsL[lr][kof];
            uint32_t* bH = (uint32_t*)&BsH[lr][kof];
            uint32_t* bL = (uint32_t*)&BsL[lr][kof];
            #pragma unroll
            for (int q = 0; q < 4; q++) {
                float v[4] = {fa[q].x, fa[q].y, fa[q].z, fa[q].w};
                float w[4] = {fb[q].x, fb[q].y, fb[q].z, fb[q].w};
                __nv_bfloat16 vh[4], vl[4], wh[4], wl[4];
                #pragma unroll
                for (int e = 0; e < 4; e++) {
                    vh[e] = __float2bfloat16_rn(v[e]);
                    vl[e] = __float2bfloat16_rn(v[e] - __bfloat162float(vh[e]));
                    wh[e] = __float2bfloat16_rn(w[e]);
                    wl[e] = __float2bfloat16_rn(w[e] - __bfloat162float(wh[e]));
                }
                aH[q * 2 + 0] = pack_bf2(vh[0], vh[1]);
                aH[q * 2 + 1] = pack_bf2(vh[2], vh[3]);
                aL[q * 2 + 0] = pack_bf2(vl[0], vl[1]);
                aL[q * 2 + 1] = pack_bf2(vl[2], vl[3]);
                bH[q * 2 + 0] = pack_bf2(wh[0], wh[1]);
                bH[q * 2 + 1] = pack_bf2(wh[2], wh[3]);
                bL[q * 2 + 0] = pack_bf2(wl[0], wl[1]);
                bL[q * 2 + 1] = pack_bf2(wl[2], wl[3]);
            }
        }
        __syncthreads();

        // ---- compute: 2 k16 steps ----
        #pragma unroll
        for (int kk = 0; kk < KC; kk += 16) {
            uint32_t aHf[4][4], aLf[4][4];
            #pragma unroll
            for (int mt = 0; mt < 4; mt++) {
                int r0 = wm * 64 + mt * 16 + g;
                aHf[mt][0] = *(uint32_t*)&AsH[r0][kk + 2 * tig];
                aHf[mt][1] = *(uint32_t*)&AsH[r0 + 8][kk + 2 * tig];
                aHf[mt][2] = *(uint32_t*)&AsH[r0][kk + 2 * tig + 8];
                aHf[mt][3] = *(uint32_t*)&AsH[r0 + 8][kk + 2 * tig + 8];
                aLf[mt][0] = *(uint32_t*)&AsL[r0][kk + 2 * tig];
                aLf[mt][1] = *(uint32_t*)&AsL[r0 + 8][kk + 2 * tig];
                aLf[mt][2] = *(uint32_t*)&AsL[r0][kk + 2 * tig + 8];
                aLf[mt][3] = *(uint32_t*)&AsL[r0 + 8][kk + 2 * tig + 8];
            }
            #pragma unroll
            for (int nt = 0; nt < 4; nt++) {
                int c0 = wn * 32 + nt * 8 + g;
                uint32_t bHf[2], bLf[2];
                bHf[0] = *(uint32_t*)&BsH[c0][kk + 2 * tig];
                bHf[1] = *(uint32_t*)&BsH[c0][kk + 2 * tig + 8];
                bLf[0] = *(uint32_t*)&BsL[c0][kk + 2 * tig];
                bLf[1] = *(uint32_t*)&BsL[c0][kk + 2 * tig + 8];
                #pragma unroll
                for (int mt = 0; mt < 4; mt++) {
                    mma_bf16(acc[mt][nt], aHf[mt], bHf);  // hi*hi
                    mma_bf16(acc[mt][nt], aHf[mt], bLf);  // hi*lo
                    mma_bf16(acc[mt][nt], aLf[mt], bHf);  // lo*hi
                }
            }
        }
    }

    // ---- epilogue ----
    #pragma unroll
    for (int mt = 0; mt < 4; mt++) {
        #pragma unroll
        for (int rr = 0; rr < 2; rr++) {
            int r = bm + wm * 64 + mt * 16 + g + rr * 8;
            int bb = r >> 9;
            #pragma unroll
            for (int nt = 0; nt < 4; nt++) {
                int c = bn + wn * 32 + nt * 8 + 2 * tig;
                float v0 = acc[mt][nt][rr * 2 + 0] + bias[c];
                float v1 = acc[mt][nt][rr * 2 + 1] + bias[c + 1];
                if (EPI == 1) { v0 = v0 * normcdff(v0); v1 = v1 * normcdff(v1); }
                size_t off = (size_t)r * N + c;
                if (EPI == 2) {
                    v0 = res[off]     + gate[bb * MODS + c]     * v0;
                    v1 = res[off + 1] + gate[bb * MODS + c + 1] * v1;
                }
                *(float2*)(C + off) = make_float2(v0, v1);
            }
        }
    }
}

// ============================================================
// 4) Rel-pos bias MLP (2 -> 64 relu -> 16), mask folded as -inf
// ============================================================
__global__ void relpos_k(const float* __restrict__ rel,
                         const float* __restrict__ w1, const float* __restrict__ b1,
                         const float* __restrict__ w2, const float* __restrict__ b2,
                         const int* __restrict__ mask) {
    __shared__ float W1[128], B1[64], W2[16 * 64], B2[16];
    int tid = threadIdx.x;
    if (tid < 128) W1[tid] = w1[tid];
    if (tid < 64)  B1[tid] = b1[tid];
    for (int i = tid; i < 1024; i += 256) W2[i] = w2[i];
    if (tid < 16)  B2[tid] = b2[tid];
    __syncthreads();
    int b = blockIdx.z, n = blockIdx.y, m = blockIdx.x * 256 + tid;
    float2 r = *(const float2*)(rel + ((size_t)((b * Nseq + n) * Nseq + m)) * 2);
    bool ok = (mask[b * Nseq + m] != 0);
    float out[16];
    #pragma unroll
    for (int t = 0; t < 16; t++) out[t] = B2[t];
    #pragma unroll 16
    for (int j = 0; j < 64; j++) {
        float hj = fmaxf(fmaf(W1[2 * j], r.x, fmaf(W1[2 * j + 1], r.y, B1[j])), 0.0f);
        #pragma unroll
        for (int t = 0; t < 16; t++) out[t] = fmaf(W2[t * 64 + j], hj, out[t]);
    }
    #pragma unroll
    for (int t = 0; t < 16; t++) {
        size_t idx = (((size_t)(b * Hh + t) * Nseq) + n) * Nseq + m;
        g_bias[idx] = ok ? out[t] : -INFINITY;
    }
}

// ============================================================
// 5) Attention scores: S = 0.125*q.k + bias (64x64 tiles)
// ============================================================
__global__ void scores_k() {
    __shared__ float Qs[64][65], Ks[64][65];
    int bh = blockIdx.z, b = bh >> 4, h = bh & 15;
    int n0 = blockIdx.y * 64, m0 = blockIdx.x * 64;
    int tid = threadIdx.x;
    int lrow = tid >> 2, lcol = (tid & 3) * 16;
    const float* qb = g_qkv + (size_t)(b * Nseq + n0 + lrow) * 3072 + h * 64 + lcol;
    const float* kb = g_qkv + (size_t)(b * Nseq + m0 + lrow) * 3072 + 1024 + h * 64 + lcol;
    #pragma unroll
    for (int q = 0; q < 4; q++) {
        float4 v = ((const float4*)qb)[q];
        Qs[lrow][lcol + q * 4 + 0] = v.x; Qs[lrow][lcol + q * 4 + 1] = v.y;
        Qs[lrow][lcol + q * 4 + 2] = v.z; Qs[lrow][lcol + q * 4 + 3] = v.w;
        float4 w = ((const float4*)kb)[q];
        Ks[lrow][lcol + q * 4 + 0] = w.x; Ks[lrow][lcol + q * 4 + 1] = w.y;
        Ks[lrow][lcol + q * 4 + 2] = w.z; Ks[lrow][lcol + q * 4 + 3] = w.w;
    }
    __syncthreads();
    int tx = tid & 15, ty = tid >> 4;
    float acc[4][4] = {};
    #pragma unroll 8
    for (int k = 0; k < 64; k++) {
        float ar[4], br[4];
        #pragma unroll
        for (int i = 0; i < 4; i++) ar[i] = Qs[ty * 4 + i][k];
        #pragma unroll
        for (int j = 0; j < 4; j++) br[j] = Ks[tx * 4 + j][k];
        #pragma unroll
        for (int i = 0; i < 4; i++)
            #pragma unroll
            for (int j = 0; j < 4; j++)
                acc[i][j] = fmaf(ar[i], br[j], acc[i][j]);
    }
    #pragma unroll
    for (int i = 0; i < 4; i++) {
        int n = n0 + ty * 4 + i;
        #pragma unroll
        for (int j = 0; j < 4; j++) {
            int m = m0 + tx * 4 + j;
            size_t idx = ((size_t)bh * Nseq + n) * Nseq + m;
            g_scores[idx] = fmaf(acc[i][j], 0.125f, g_bias[idx]);
        }
    }
}

// ============================================================
// 6) Row softmax over m (512), one warp per row
// ============================================================
__global__ void softmax_k() {
    int row = blockIdx.x * 8 + (threadIdx.x >> 5);
    int lane = threadIdx.x & 31;
    float* p = g_scores + (size_t)row * Nseq;
    float vals[16];
    float mx = -INFINITY;
    #pragma unroll
    for (int i = 0; i < 16; i++) { vals[i] = p[lane + i * 32]; mx = fmaxf(mx, vals[i]); }
    #pragma unroll
    for (int s = 16; s; s >>= 1) mx = fmaxf(mx, __shfl_xor_sync(0xffffffff, mx, s));
    float sum = 0.0f;
    #pragma unroll
    for (int i = 0; i < 16; i++) { vals[i] = __expf(vals[i] - mx); sum += vals[i]; }
    #pragma unroll
    for (int s = 16; s; s >>= 1) sum += __shfl_xor_sync(0xffffffff, sum, s);
    float inv = 1.0f / sum;
    #pragma unroll
    for (int i = 0; i < 16; i++) p[lane + i * 32] = vals[i] * inv;
}

// ============================================================
// 7) P @ V : out[b,n,h,d]
// ============================================================
__global__ void pv_k() {
    __shared__ float Ps[64][65], Vs[64][65];
    int bh = blockIdx.y, b = bh >> 4, h = bh & 15;
    int n0 = blockIdx.x * 64;
    int tid = threadIdx.x;
    int lrow = tid >> 2, lcol = (tid & 3) * 16;
    int tx = tid & 15, ty = tid >> 4;
    float acc[4][4] = {};
    for (int m0 = 0; m0 < Nseq; m0 += 64) {
        const float* pb = g_scores + ((size_t)bh * Nseq + n0 + lrow) * Nseq + m0 + lcol;
        const float* vb = g_qkv + (size_t)(b * Nseq + m0 + lrow) * 3072 + 2048 + h * 64 + lcol;
        __syncthreads();
        #pragma unroll
        for (int q = 0; q < 4; q++) {
            float4 v = ((const float4*)pb)[q];
            Ps[lrow][lcol + q * 4 + 0] = v.x; Ps[lrow][lcol + q * 4 + 1] = v.y;
            Ps[lrow][lcol + q * 4 + 2] = v.z; Ps[lrow][lcol + q * 4 + 3] = v.w;
            float4 w = ((const float4*)vb)[q];
            Vs[lrow][lcol + q * 4 + 0] = w.x; Vs[lrow][lcol + q * 4 + 1] = w.y;
            Vs[lrow][lcol + q * 4 + 2] = w.z; Vs[lrow][lcol + q * 4 + 3] = w.w;
        }
        __syncthreads();
        #pragma unroll 8
        for (int k = 0; k < 64; k++) {
            float ar[4], br[4];
            #pragma unroll
            for (int i = 0; i < 4; i++) ar[i] = Ps[ty * 4 + i][k];
            #pragma unroll
            for (int j = 0; j < 4; j++) br[j] = Vs[k][tx * 4 + j];
            #pragma unroll
            for (int i = 0; i < 4; i++)
                #pragma unroll
                for (int j = 0; j < 4; j++)
                    acc[i][j] = fmaf(ar[i], br[j], acc[i][j]);
        }
    }
    #pragma unroll
    for (int i = 0; i < 4; i++) {
        int n = n0 + ty * 4 + i;
        #pragma unroll
        for (int j = 0; j < 4; j++) {
            g_attn[(size_t)(b * Nseq + n) * Dd + h * 64 + tx * 4 + j] = acc[i][j];
        }
    }
}

// ============================================================
// host-side launcher
// ============================================================
extern "C" void kernel_launch(void* const* d_in, const int* in_sizes, int n_in,
                              void* d_out, int out_size) {
    const float* x      = (const float*)d_in[0];
    const float* t_emb  = (const float*)d_in[1];
    const float* rel    = (const float*)d_in[2];
    const int*   mask   = (const int*)d_in[3];
    const float* w_ada  = (const float*)d_in[4];
    const float* b_ada  = (const float*)d_in[5];
    const float* g1     = (const float*)d_in[6];
    const float* beta1  = (const float*)d_in[7];
    const float* g2     = (const float*)d_in[8];
    const float* beta2  = (const float*)d_in[9];
    const float* w_qkv  = (const float*)d_in[10];
    const float* b_qkv  = (const float*)d_in[11];
    const float* w_proj = (const float*)d_in[12];
    const float* b_proj = (const float*)d_in[13];
    const float* w_rp1  = (const float*)d_in[14];
    const float* b_rp1  = (const float*)d_in[15];
    const float* w_rp2  = (const float*)d_in[16];
    const float* b_rp2  = (const float*)d_in[17];
    const float* w_fc1  = (const float*)d_in[18];
    const float* b_fc1  = (const float*)d_in[19];
    const float* w_fc2  = (const float*)d_in[20];
    const float* b_fc2  = (const float*)d_in[21];
    float* out = (float*)d_out;

    void *p_mod, *p_xn, *p_qkv, *p_attn, *p_x1, *p_h;
    cudaGetSymbolAddress(&p_mod,  g_mod);
    cudaGetSymbolAddress(&p_xn,   g_xn);
    cudaGetSymbolAddress(&p_qkv,  g_qkv);
    cudaGetSymbolAddress(&p_attn, g_attn);
    cudaGetSymbolAddress(&p_x1,   g_x1);
    cudaGetSymbolAddress(&p_h,    g_hbuf);
    float* modf = (float*)p_mod;

    // 1. adaLN modulation
    adaln_k<<<dim3(768, 4), 256>>>(t_emb, w_ada, b_ada);
    // 2. LN1 + modulate (shift_s @ 0, scale_s @ D)
    ln_mod_k<<<MM, 256>>>(x, g1, beta1, 0, Dd, (float*)p_xn);
    // 3. QKV projection (tensor cores, split-bf16)
    gemm_tc<0><<<dim3(3072 / 128, MM / 128), 256>>>(
        (const float*)p_xn, w_qkv, b_qkv, nullptr, nullptr, (float*)p_qkv, MM, 3072, Dd);
    // 4. rel-pos bias (+key mask folded in)
    relpos_k<<<dim3(2, Nseq, Bb), 256>>>(rel, w_rp1, b_rp1, w_rp2, b_rp2, mask);
    // 5. scores
    scores_k<<<dim3(8, 8, Bb * Hh), 256>>>();
    // 6. softmax
    softmax_k<<<(Bb * Hh * Nseq) / 8, 256>>>();
    // 7. P @ V
    pv_k<<<dim3(8, Bb * Hh), 256>>>();
    // 8. proj + residual with gate_s (chunk 2)
    gemm_tc<2><<<dim3(1024 / 128, MM / 128), 256>>>(
        (const float*)p_attn, w_proj, b_proj, x, modf + 2 * Dd, (float*)p_x1, MM, Dd, Dd);
    // 9. LN2 + modulate (shift_m @ 3D, scale_m @ 4D)
    ln_mod_k<<<MM, 256>>>((const float*)p_x1, g2, beta2, 3 * Dd, 4 * Dd, (float*)p_xn);
    // 10. fc1 + exact GELU
    gemm_tc<1><<<dim3(HIDd / 128, MM / 128), 256>>>(
        (const float*)p_xn, w_fc1, b_fc1, nullptr, nullptr, (float*)p_h, MM, HIDd, Dd);
    // 11. fc2 + residual with gate_m (chunk 5) -> final output
    gemm_tc<2><<<dim3(1024 / 128, MM / 128), 256>>>(
        (const float*)p_h, w_fc2, b_fc2, (const float*)p_x1, modf + 5 * Dd, out, MM, Dd, HIDd);
}

// round 6
// speedup vs baseline: 1.9502x; 1.1148x over previous
#include <cuda_runtime.h>
#include <cuda_bf16.h>
#include <stdint.h>
#include <math.h>

// Problem constants
#define Bb   4
#define Nseq 512
#define Dd   1024
#define Hh   16
#define HDd  64
#define HIDd 4096
#define MM   (Bb * Nseq)     // 2048 rows
#define MODS (6 * Dd)        // 6144

// ---- scratch (no allocs allowed -> __device__ globals) ----
__device__ float g_mod[Bb * MODS];
__device__ float g_qkv[MM * 3 * Dd];
__device__ float g_bias[(size_t)Bb * Hh * Nseq * Nseq];
__device__ float g_scores[(size_t)Bb * Hh * Nseq * Nseq];
__device__ float g_x1[MM * Dd];

// hi/lo bf16 planes (packed 2 elems per uint32 where written by vector paths)
__device__ __align__(16) __nv_bfloat16 g_xnH[MM * Dd];
__device__ __align__(16) __nv_bfloat16 g_xnL[MM * Dd];
__device__ uint32_t g_attnH[MM * Dd / 2];
__device__ uint32_t g_attnL[MM * Dd / 2];
__device__ uint32_t g_hH[(size_t)MM * HIDd / 2];
__device__ uint32_t g_hL[(size_t)MM * HIDd / 2];
// weight planes
__device__ uint32_t g_wqkvH[3 * Dd * Dd / 2];
__device__ uint32_t g_wqkvL[3 * Dd * Dd / 2];
__device__ uint32_t g_wprojH[Dd * Dd / 2];
__device__ uint32_t g_wprojL[Dd * Dd / 2];
__device__ uint32_t g_wfc1H[(size_t)HIDd * Dd / 2];
__device__ uint32_t g_wfc1L[(size_t)HIDd * Dd / 2];
__device__ uint32_t g_wfc2H[(size_t)Dd * HIDd / 2];
__device__ uint32_t g_wfc2L[(size_t)Dd * HIDd / 2];

__device__ __forceinline__ uint32_t pack_bf2(__nv_bfloat16 a, __nv_bfloat16 b) {
    unsigned short ua = *(unsigned short*)&a;
    unsigned short ub = *(unsigned short*)&b;
    return ((uint32_t)ub << 16) | ua;
}

__device__ __forceinline__ void split2(float x, float y, uint32_t& h, uint32_t& l) {
    __nv_bfloat16 hx = __float2bfloat16_rn(x);
    __nv_bfloat16 hy = __float2bfloat16_rn(y);
    __nv_bfloat16 lx = __float2bfloat16_rn(x - __bfloat162float(hx));
    __nv_bfloat16 ly = __float2bfloat16_rn(y - __bfloat162float(hy));
    h = pack_bf2(hx, hy);
    l = pack_bf2(lx, ly);
}

__device__ __forceinline__ void mma_bf16(float* c, const uint32_t* a, const uint32_t* b) {
    asm volatile(
        "mma.sync.aligned.m16n8k16.row.col.f32.bf16.bf16.f32 "
        "{%0,%1,%2,%3}, {%4,%5,%6,%7}, {%8,%9}, {%0,%1,%2,%3};"
        : "+f"(c[0]), "+f"(c[1]), "+f"(c[2]), "+f"(c[3])
        : "r"(a[0]), "r"(a[1]), "r"(a[2]), "r"(a[3]), "r"(b[0]), "r"(b[1]));
}

// ============================================================
// 0) weight hi/lo split: fp32 -> packed bf16 hi/lo planes
// ============================================================
__global__ void cvtw_k(const float* __restrict__ src,
                       uint32_t* __restrict__ h, uint32_t* __restrict__ l) {
    int i = blockIdx.x * 256 + threadIdx.x;
    float2 v = ((const float2*)src)[i];
    uint32_t hh, ll;
    split2(v.x, v.y, hh, ll);
    h[i] = hh; l[i] = ll;
}

// ============================================================
// 1) adaLN: mod = silu(t_emb) @ w_ada^T + b_ada   [B, 6144]
// ============================================================
__global__ void adaln_k(const float* __restrict__ t_emb,
                        const float* __restrict__ w,
                        const float* __restrict__ bias) {
    __shared__ float st[Dd];
    int b = blockIdx.y;
    for (int i = threadIdx.x; i < Dd; i += 256) {
        float t = t_emb[b * Dd + i];
        st[i] = t / (1.0f + expf(-t));
    }
    __syncthreads();
    int warp = threadIdx.x >> 5, lane = threadIdx.x & 31;
    int o = blockIdx.x * 8 + warp;
    const float* wr = w + (size_t)o * Dd;
    float acc = 0.0f;
    for (int k = lane; k < Dd; k += 32) acc = fmaf(st[k], wr[k], acc);
    #pragma unroll
    for (int s = 16; s; s >>= 1) acc += __shfl_xor_sync(0xffffffff, acc, s);
    if (lane == 0) g_mod[b * MODS + o] = acc + bias[o];
}

// ============================================================
// 2) LayerNorm + adaLN modulate -> bf16 hi/lo planes
// ============================================================
__global__ void ln_mod_k(const float* __restrict__ x,
                         const float* __restrict__ g,
                         const float* __restrict__ beta,
                         int shiftOff, int scaleOff,
                         __nv_bfloat16* __restrict__ outH,
                         __nv_bfloat16* __restrict__ outL) {
    int row = blockIdx.x;
    int b = row >> 9;
    const float* xr = x + (size_t)row * Dd;
    __shared__ float r1[256], r2[256];
    float s = 0.0f, s2 = 0.0f;
    for (int j = threadIdx.x; j < Dd; j += 256) {
        float v = xr[j];
        s += v; s2 = fmaf(v, v, s2);
    }
    r1[threadIdx.x] = s; r2[threadIdx.x] = s2;
    __syncthreads();
    for (int st = 128; st; st >>= 1) {
        if (threadIdx.x < st) {
            r1[threadIdx.x] += r1[threadIdx.x + st];
            r2[threadIdx.x] += r2[threadIdx.x + st];
        }
        __syncthreads();
    }
    float mu = r1[0] * (1.0f / Dd);
    float var = r2[0] * (1.0f / Dd) - mu * mu;
    float rstd = rsqrtf(var + 1e-5f);
    const float* sh = g_mod + b * MODS + shiftOff;
    const float* sc = g_mod + b * MODS + scaleOff;
    __nv_bfloat16* oh = outH + (size_t)row * Dd;
    __nv_bfloat16* ol = outL + (size_t)row * Dd;
    for (int j = threadIdx.x; j < Dd; j += 256) {
        float v = (xr[j] - mu) * rstd * g[j] + beta[j];
        float m = fmaf(v, 1.0f + sc[j], sh[j]);
        __nv_bfloat16 h = __float2bfloat16_rn(m);
        oh[j] = h;
        ol[j] = __float2bfloat16_rn(m - __bfloat162float(h));
    }
}

// ============================================================
// 3) Tensor-core NT GEMM on precomputed bf16 hi/lo planes.
//    Block 128x128x32, 8 warps, warp tile 64x32 (m16n8k16 MMAs).
//    EPI: 0 plain fp32 out, 1 exact GELU -> hi/lo plane out,
//         2 residual + per-(batch,col) gate -> fp32 out
// ============================================================
#define SPITCH 40      // smem row pitch in bf16 elems (80B)

template <int EPI>
__global__ void __launch_bounds__(256, 2)
gemm_tc(const uint32_t* __restrict__ AH, const uint32_t* __restrict__ AL,
        const uint32_t* __restrict__ BH, const uint32_t* __restrict__ BL,
        const float* __restrict__ bias, const float* __restrict__ res,
        const float* __restrict__ gate, float* __restrict__ C,
        uint32_t* __restrict__ CH, uint32_t* __restrict__ CL,
        int M, int N, int K) {
    __shared__ __nv_bfloat16 AsH[128][SPITCH], AsL[128][SPITCH];
    __shared__ __nv_bfloat16 BsH[128][SPITCH], BsL[128][SPITCH];

    int bm = blockIdx.y * 128, bn = blockIdx.x * 128;
    int tid = threadIdx.x;
    int warp = tid >> 5, lane = tid & 31;
    int wm = warp >> 2, wn = warp & 3;
    int g = lane >> 2, tig = lane & 3;

    int lr   = tid >> 1;
    int kofu = (tid & 1) * 8;     // u32 offset (8 u32 = 16 elems per half)
    int kofe = (tid & 1) * 16;    // element offset

    float acc[4][4][4] = {};
    int K2 = K >> 1;
    const uint32_t* AHp = AH + (size_t)(bm + lr) * K2 + kofu;
    const uint32_t* ALp = AL + (size_t)(bm + lr) * K2 + kofu;
    const uint32_t* BHp = BH + (size_t)(bn + lr) * K2 + kofu;
    const uint32_t* BLp = BL + (size_t)(bn + lr) * K2 + kofu;

    for (int k0 = 0; k0 < K2; k0 += 16) {   // 32 elems per iter
        uint4 vah0 = *(const uint4*)(AHp + k0);
        uint4 vah1 = *(const uint4*)(AHp + k0 + 4);
        uint4 val0 = *(const uint4*)(ALp + k0);
        uint4 val1 = *(const uint4*)(ALp + k0 + 4);
        uint4 vbh0 = *(const uint4*)(BHp + k0);
        uint4 vbh1 = *(const uint4*)(BHp + k0 + 4);
        uint4 vbl0 = *(const uint4*)(BLp + k0);
        uint4 vbl1 = *(const uint4*)(BLp + k0 + 4);
        __syncthreads();
        *(uint4*)&AsH[lr][kofe]     = vah0;
        *(uint4*)&AsH[lr][kofe + 8] = vah1;
        *(uint4*)&AsL[lr][kofe]     = val0;
        *(uint4*)&AsL[lr][kofe + 8] = val1;
        *(uint4*)&BsH[lr][kofe]     = vbh0;
        *(uint4*)&BsH[lr][kofe + 8] = vbh1;
        *(uint4*)&BsL[lr][kofe]     = vbl0;
        *(uint4*)&BsL[lr][kofe + 8] = vbl1;
        __syncthreads();

        #pragma unroll
        for (int kk = 0; kk < 32; kk += 16) {
            uint32_t aHf[4][4], aLf[4][4];
            #pragma unroll
            for (int mt = 0; mt < 4; mt++) {
                int r0 = wm * 64 + mt * 16 + g;
                aHf[mt][0] = *(uint32_t*)&AsH[r0][kk + 2 * tig];
                aHf[mt][1] = *(uint32_t*)&AsH[r0 + 8][kk + 2 * tig];
                aHf[mt][2] = *(uint32_t*)&AsH[r0][kk + 2 * tig + 8];
                aHf[mt][3] = *(uint32_t*)&AsH[r0 + 8][kk + 2 * tig + 8];
                aLf[mt][0] = *(uint32_t*)&AsL[r0][kk + 2 * tig];
                aLf[mt][1] = *(uint32_t*)&AsL[r0 + 8][kk + 2 * tig];
                aLf[mt][2] = *(uint32_t*)&AsL[r0][kk + 2 * tig + 8];
                aLf[mt][3] = *(uint32_t*)&AsL[r0 + 8][kk + 2 * tig + 8];
            }
            #pragma unroll
            for (int nt = 0; nt < 4; nt++) {
                int c0 = wn * 32 + nt * 8 + g;
                uint32_t bHf[2], bLf[2];
                bHf[0] = *(uint32_t*)&BsH[c0][kk + 2 * tig];
                bHf[1] = *(uint32_t*)&BsH[c0][kk + 2 * tig + 8];
                bLf[0] = *(uint32_t*)&BsL[c0][kk + 2 * tig];
                bLf[1] = *(uint32_t*)&BsL[c0][kk + 2 * tig + 8];
                #pragma unroll
                for (int mt = 0; mt < 4; mt++) {
                    mma_bf16(acc[mt][nt], aHf[mt], bHf);
                    mma_bf16(acc[mt][nt], aHf[mt], bLf);
                    mma_bf16(acc[mt][nt], aLf[mt], bHf);
                }
            }
        }
    }

    // ---- epilogue ----
    #pragma unroll
    for (int mt = 0; mt < 4; mt++) {
        #pragma unroll
        for (int rr = 0; rr < 2; rr++) {
            int r = bm + wm * 64 + mt * 16 + g + rr * 8;
            int bb = r >> 9;
            #pragma unroll
            for (int nt = 0; nt < 4; nt++) {
                int c = bn + wn * 32 + nt * 8 + 2 * tig;
                float v0 = acc[mt][nt][rr * 2 + 0] + bias[c];
                float v1 = acc[mt][nt][rr * 2 + 1] + bias[c + 1];
                size_t off = (size_t)r * N + c;
                if (EPI == 1) {
                    v0 = v0 * normcdff(v0);
                    v1 = v1 * normcdff(v1);
                    uint32_t hh, ll;
                    split2(v0, v1, hh, ll);
                    CH[off >> 1] = hh; CL[off >> 1] = ll;
                } else {
                    if (EPI == 2) {
                        v0 = res[off]     + gate[bb * MODS + c]     * v0;
                        v1 = res[off + 1] + gate[bb * MODS + c + 1] * v1;
                    }
                    *(float2*)(C + off) = make_float2(v0, v1);
                }
            }
        }
    }
}

// ============================================================
// 4) Rel-pos bias MLP (2 -> 64 relu -> 16), mask folded as -inf
//    4 pairs per thread, W2 transposed in smem, float4 reads.
// ============================================================
__global__ void __launch_bounds__(128)
relpos_k(const float* __restrict__ rel,
         const float* __restrict__ w1, const float* __restrict__ b1,
         const float* __restrict__ w2, const float* __restrict__ b2,
         const int* __restrict__ mask) {
    __shared__ float W1[128], B1[64], W2T[64][16], B2s[16];
    int tid = threadIdx.x;
    if (tid < 128) W1[tid] = w1[tid];
    if (tid < 64)  B1[tid] = b1[tid];
    for (int i = tid; i < 1024; i += 128) {
        int j = i >> 4, t = i & 15;
        W2T[j][t] = w2[t * 64 + j];
    }
    if (tid < 16)  B2s[tid] = b2[tid];
    __syncthreads();
    int b = blockIdx.y, n = blockIdx.x;
    const float* rbase = rel + ((size_t)(b * Nseq + n) * Nseq) * 2;
    float2 r[4]; bool ok[4];
    #pragma unroll
    for (int i = 0; i < 4; i++) {
        int m = tid + 128 * i;
        r[i] = *(const float2*)(rbase + 2 * m);
        ok[i] = (mask[b * Nseq + m] != 0);
    }
    float out[4][16];
    #pragma unroll
    for (int i = 0; i < 4; i++)
        #pragma unroll
        for (int t = 0; t < 16; t++) out[i][t] = B2s[t];
    #pragma unroll 8
    for (int j = 0; j < 64; j++) {
        float w1x = W1[2 * j], w1y = W1[2 * j + 1], bb = B1[j];
        float hj[4];
        #pragma unroll
        for (int i = 0; i < 4; i++)
            hj[i] = fmaxf(fmaf(w1x, r[i].x, fmaf(w1y, r[i].y, bb)), 0.0f);
        float4 w0 = *(const float4*)&W2T[j][0];
        float4 w4 = *(const float4*)&W2T[j][4];
        float4 w8 = *(const float4*)&W2T[j][8];
        float4 wc = *(const float4*)&W2T[j][12];
        float wv[16] = {w0.x, w0.y, w0.z, w0.w, w4.x, w4.y, w4.z, w4.w,
                        w8.x, w8.y, w8.z, w8.w, wc.x, wc.y, wc.z, wc.w};
        #pragma unroll
        for (int i = 0; i < 4; i++)
            #pragma unroll
            for (int t = 0; t < 16; t++)
                out[i][t] = fmaf(wv[t], hj[i], out[i][t]);
    }
    #pragma unroll
    for (int t = 0; t < 16; t++) {
        #pragma unroll
        for (int i = 0; i < 4; i++) {
            int m = tid + 128 * i;
            size_t idx = (((size_t)(b * Hh + t) * Nseq) + n) * Nseq + m;
            g_bias[idx] = ok[i] ? out[i][t] : -INFINITY;
        }
    }
}

// ============================================================
// 5) Attention scores via tensor cores (hi/lo 3-MMA):
//    S[n,m] = 0.125 * Q.K + bias, 64x64 tile, 4 warps.
// ============================================================
__global__ void __launch_bounds__(128)
scores_tc() {
    __shared__ __nv_bfloat16 QH[64][72], QL[64][72], KH[64][72], KL[64][72];
    int bh = blockIdx.z, b = bh >> 4, h = bh & 15;
    int n0 = blockIdx.y * 64, m0 = blockIdx.x * 64;
    int tid = threadIdx.x;
    int warp = tid >> 5, lane = tid & 31;
    int g = lane >> 2, tig = lane & 3;
    int srow = tid >> 1, kof = (tid & 1) * 32;

    const float* qb = g_qkv + (size_t)(b * Nseq + n0 + srow) * 3072 + h * 64 + kof;
    const float* kb = g_qkv + (size_t)(b * Nseq + m0 + srow) * 3072 + 1024 + h * 64 + kof;
    #pragma unroll
    for (int q = 0; q < 8; q++) {
        float4 v = ((const float4*)qb)[q];
        uint32_t h0, l0, h1, l1;
        split2(v.x, v.y, h0, l0);
        split2(v.z, v.w, h1, l1);
        *(uint32_t*)&QH[srow][kof + q * 4]     = h0;
        *(uint32_t*)&QH[srow][kof + q * 4 + 2] = h1;
        *(uint32_t*)&QL[srow][kof + q * 4]     = l0;
        *(uint32_t*)&QL[srow][kof + q * 4 + 2] = l1;
        float4 w = ((const float4*)kb)[q];
        split2(w.x, w.y, h0, l0);
        split2(w.z, w.w, h1, l1);
        *(uint32_t*)&KH[srow][kof + q * 4]     = h0;
        *(uint32_t*)&KH[srow][kof + q * 4 + 2] = h1;
        *(uint32_t*)&KL[srow][kof + q * 4]     = l0;
        *(uint32_t*)&KL[srow][kof + q * 4 + 2] = l1;
    }
    __syncthreads();

    float acc[8][4] = {};
    #pragma unroll
    for (int kk = 0; kk < 64; kk += 16) {
        uint32_t aH[4], aL[4];
        int r0 = warp * 16 + g;
        aH[0] = *(uint32_t*)&QH[r0][kk + 2 * tig];
        aH[1] = *(uint32_t*)&QH[r0 + 8][kk + 2 * tig];
        aH[2] = *(uint32_t*)&QH[r0][kk + 2 * tig + 8];
        aH[3] = *(uint32_t*)&QH[r0 + 8][kk + 2 * tig + 8];
        aL[0] = *(uint32_t*)&QL[r0][kk + 2 * tig];
        aL[1] = *(uint32_t*)&QL[r0 + 8][kk + 2 * tig];
        aL[2] = *(uint32_t*)&QL[r0][kk + 2 * tig + 8];
        aL[3] = *(uint32_t*)&QL[r0 + 8][kk + 2 * tig + 8];
        #pragma unroll
        for (int nt = 0; nt < 8; nt++) {
            int c0 = nt * 8 + g;
            uint32_t bH[2], bL[2];
            bH[0] = *(uint32_t*)&KH[c0][kk + 2 * tig];
            bH[1] = *(uint32_t*)&KH[c0][kk + 2 * tig + 8];
            bL[0] = *(uint32_t*)&KL[c0][kk + 2 * tig];
            bL[1] = *(uint32_t*)&KL[c0][kk + 2 * tig + 8];
            mma_bf16(acc[nt], aH, bH);
            mma_bf16(acc[nt], aH, bL);
            mma_bf16(acc[nt], aL, bH);
        }
    }
    #pragma unroll
    for (int nt = 0; nt < 8; nt++) {
        #pragma unroll
        for (int rr = 0; rr < 2; rr++) {
            int n = n0 + warp * 16 + g + rr * 8;
            int m = m0 + nt * 8 + 2 * tig;
            size_t idx = ((size_t)bh * Nseq + n) * Nseq + m;
            float2 bv = *(const float2*)&g_bias[idx];
            float2 o;
            o.x = fmaf(acc[nt][rr * 2 + 0], 0.125f, bv.x);
            o.y = fmaf(acc[nt][rr * 2 + 1], 0.125f, bv.y);
            *(float2*)&g_scores[idx] = o;
        }
    }
}

// ============================================================
// 6) Row softmax over m (512), one warp per row
// ============================================================
__global__ void softmax_k() {
    int row = blockIdx.x * 8 + (threadIdx.x >> 5);
    int lane = threadIdx.x & 31;
    float* p = g_scores + (size_t)row * Nseq;
    float vals[16];
    float mx = -INFINITY;
    #pragma unroll
    for (int i = 0; i < 16; i++) { vals[i] = p[lane + i * 32]; mx = fmaxf(mx, vals[i]); }
    #pragma unroll
    for (int s = 16; s; s >>= 1) mx = fmaxf(mx, __shfl_xor_sync(0xffffffff, mx, s));
    float sum = 0.0f;
    #pragma unroll
    for (int i = 0; i < 16; i++) { vals[i] = __expf(vals[i] - mx); sum += vals[i]; }
    #pragma unroll
    for (int s = 16; s; s >>= 1) sum += __shfl_xor_sync(0xffffffff, sum, s);
    float inv = 1.0f / sum;
    #pragma unroll
    for (int i = 0; i < 16; i++) p[lane + i * 32] = vals[i] * inv;
}

// ============================================================
// 7) P @ V via tensor cores (hi/lo 3-MMA), emits attn hi/lo planes.
//    64 q-rows per block, 4 warps, loop over 8 key tiles.
// ============================================================
__global__ void __launch_bounds__(128)
pv_tc() {
    // union region: Vs fp32 (64x68) aliased with PH/PL bf16 (2 x 64x72)
    __shared__ __align__(16) unsigned char su[2 * 64 * 72 * 2];
    float (*Vs)[68] = (float(*)[68])su;
    __nv_bfloat16 (*PH)[72] = (__nv_bfloat16(*)[72])su;
    __nv_bfloat16 (*PL)[72] = (__nv_bfloat16(*)[72])(su + 64 * 72 * 2);
    __shared__ __nv_bfloat16 VtH[64][72], VtL[64][72];

    int bh = blockIdx.y, b = bh >> 4, h = bh & 15;
    int n0 = blockIdx.x * 64;
    int tid = threadIdx.x;
    int warp = tid >> 5, lane = tid & 31;
    int g = lane >> 2, tig = lane & 3;
    int srow = tid >> 1, kof = (tid & 1) * 32;
    int dcol = tid & 63, mh = (tid >> 6) * 32;

    float acc[8][4] = {};

    for (int m0 = 0; m0 < Nseq; m0 += 64) {
        __syncthreads();
        // ---- stage V tile fp32 ----
        const float* vb = g_qkv + (size_t)(b * Nseq + m0 + srow) * 3072 + 2048 + h * 64 + kof;
        #pragma unroll
        for (int q = 0; q < 8; q++)
            *(float4*)&Vs[srow][kof + q * 4] = ((const float4*)vb)[q];
        __syncthreads();
        // ---- transpose V -> VtH/VtL (bf16 hi/lo) ----
        {
            float tv[32];
            #pragma unroll
            for (int j = 0; j < 32; j++) tv[j] = Vs[mh + j][dcol];
            #pragma unroll
            for (int e = 0; e < 16; e++) {
                uint32_t hh, ll;
                split2(tv[2 * e], tv[2 * e + 1], hh, ll);
                *(uint32_t*)&VtH[dcol][mh + 2 * e] = hh;
                *(uint32_t*)&VtL[dcol][mh + 2 * e] = ll;
            }
        }
        __syncthreads();
        // ---- stage P tile (overwrites Vs region) ----
        const float* pb = g_scores + ((size_t)bh * Nseq + n0 + srow) * Nseq + m0 + kof;
        #pragma unroll
        for (int q = 0; q < 8; q++) {
            float4 v = ((const float4*)pb)[q];
            uint32_t h0, l0, h1, l1;
            split2(v.x, v.y, h0, l0);
            split2(v.z, v.w, h1, l1);
            *(uint32_t*)&PH[srow][kof + q * 4]     = h0;
            *(uint32_t*)&PH[srow][kof + q * 4 + 2] = h1;
            *(uint32_t*)&PL[srow][kof + q * 4]     = l0;
            *(uint32_t*)&PL[srow][kof + q * 4 + 2] = l1;
        }
        __syncthreads();
        // ---- mma ----
        #pragma unroll
        for (int kk = 0; kk < 64; kk += 16) {
            uint32_t aH[4], aL[4];
            int r0 = warp * 16 + g;
            aH[0] = *(uint32_t*)&PH[r0][kk + 2 * tig];
            aH[1] = *(uint32_t*)&PH[r0 + 8][kk + 2 * tig];
            aH[2] = *(uint32_t*)&PH[r0][kk + 2 * tig + 8];
            aH[3] = *(uint32_t*)&PH[r0 + 8][kk + 2 * tig + 8];
            aL[0] = *(uint32_t*)&PL[r0][kk + 2 * tig];
            aL[1] = *(uint32_t*)&PL[r0 + 8][kk + 2 * tig];
            aL[2] = *(uint32_t*)&PL[r0][kk + 2 * tig + 8];
            aL[3] = *(uint32_t*)&PL[r0 + 8][kk + 2 * tig + 8];
            #pragma unroll
            for (int nt = 0; nt < 8; nt++) {
                int c0 = nt * 8 + g;
                uint32_t bH[2], bL[2];
                bH[0] = *(uint32_t*)&VtH[c0][kk + 2 * tig];
                bH[1] = *(uint32_t*)&VtH[c0][kk + 2 * tig + 8];
                bL[0] = *(uint32_t*)&VtL[c0][kk + 2 * tig];
                bL[1] = *(uint32_t*)&VtL[c0][kk + 2 * tig + 8];
                mma_bf16(acc[nt], aH, bH);
                mma_bf16(acc[nt], aH, bL);
                mma_bf16(acc[nt], aL, bH);
            }
        }
    }
    // ---- epilogue: write attn hi/lo planes ----
    #pragma unroll
    for (int nt = 0; nt < 8; nt++) {
        #pragma unroll
        for (int rr = 0; rr < 2; rr++) {
            int n = n0 + warp * 16 + g + rr * 8;
            int d = nt * 8 + 2 * tig;
            uint32_t hh, ll;
            split2(acc[nt][rr * 2 + 0], acc[nt][rr * 2 + 1], hh, ll);
            size_t off2 = ((size_t)(b * Nseq + n) * Dd + h * 64 + d) >> 1;
            g_attnH[off2] = hh;
            g_attnL[off2] = ll;
        }
    }
}

// ============================================================
// host-side launcher
// ============================================================
extern "C" void kernel_launch(void* const* d_in, const int* in_sizes, int n_in,
                              void* d_out, int out_size) {
    const float* x      = (const float*)d_in[0];
    const float* t_emb  = (const float*)d_in[1];
    const float* rel    = (const float*)d_in[2];
    const int*   mask   = (const int*)d_in[3];
    const float* w_ada  = (const float*)d_in[4];
    const float* b_ada  = (const float*)d_in[5];
    const float* g1     = (const float*)d_in[6];
    const float* beta1  = (const float*)d_in[7];
    const float* g2     = (const float*)d_in[8];
    const float* beta2  = (const float*)d_in[9];
    const float* w_qkv  = (const float*)d_in[10];
    const float* b_qkv  = (const float*)d_in[11];
    const float* w_proj = (const float*)d_in[12];
    const float* b_proj = (const float*)d_in[13];
    const float* w_rp1  = (const float*)d_in[14];
    const float* b_rp1  = (const float*)d_in[15];
    const float* w_rp2  = (const float*)d_in[16];
    const float* b_rp2  = (const float*)d_in[17];
    const float* w_fc1  = (const float*)d_in[18];
    const float* b_fc1  = (const float*)d_in[19];
    const float* w_fc2  = (const float*)d_in[20];
    const float* b_fc2  = (const float*)d_in[21];
    float* out = (float*)d_out;

    void *p_mod, *p_qkv, *p_x1;
    void *p_xnH, *p_xnL, *p_attnH, *p_attnL, *p_hH, *p_hL;
    void *p_wqkvH, *p_wqkvL, *p_wprojH, *p_wprojL, *p_wfc1H, *p_wfc1L, *p_wfc2H, *p_wfc2L;
    cudaGetSymbolAddress(&p_mod,  g_mod);
    cudaGetSymbolAddress(&p_qkv,  g_qkv);
    cudaGetSymbolAddress(&p_x1,   g_x1);
    cudaGetSymbolAddress(&p_xnH,  g_xnH);
    cudaGetSymbolAddress(&p_xnL,  g_xnL);
    cudaGetSymbolAddress(&p_attnH, g_attnH);
    cudaGetSymbolAddress(&p_attnL, g_attnL);
    cudaGetSymbolAddress(&p_hH,   g_hH);
    cudaGetSymbolAddress(&p_hL,   g_hL);
    cudaGetSymbolAddress(&p_wqkvH, g_wqkvH);
    cudaGetSymbolAddress(&p_wqkvL, g_wqkvL);
    cudaGetSymbolAddress(&p_wprojH, g_wprojH);
    cudaGetSymbolAddress(&p_wprojL, g_wprojL);
    cudaGetSymbolAddress(&p_wfc1H, g_wfc1H);
    cudaGetSymbolAddress(&p_wfc1L, g_wfc1L);
    cudaGetSymbolAddress(&p_wfc2H, g_wfc2H);
    cudaGetSymbolAddress(&p_wfc2L, g_wfc2L);
    float* modf = (float*)p_mod;

    // 0. weight hi/lo planes
    cvtw_k<<<(3 * Dd * Dd / 2) / 256, 256>>>(w_qkv, (uint32_t*)p_wqkvH, (uint32_t*)p_wqkvL);
    cvtw_k<<<(Dd * Dd / 2) / 256, 256>>>(w_proj, (uint32_t*)p_wprojH, (uint32_t*)p_wprojL);
    cvtw_k<<<(HIDd * Dd / 2) / 256, 256>>>(w_fc1, (uint32_t*)p_wfc1H, (uint32_t*)p_wfc1L);
    cvtw_k<<<(Dd * HIDd / 2) / 256, 256>>>(w_fc2, (uint32_t*)p_wfc2H, (uint32_t*)p_wfc2L);
    // 1. adaLN modulation
    adaln_k<<<dim3(768, 4), 256>>>(t_emb, w_ada, b_ada);
    // 2. LN1 + modulate -> xn planes
    ln_mod_k<<<MM, 256>>>(x, g1, beta1, 0, Dd,
                          (__nv_bfloat16*)p_xnH, (__nv_bfloat16*)p_xnL);
    // 3. QKV projection
    gemm_tc<0><<<dim3(3072 / 128, MM / 128), 256>>>(
        (const uint32_t*)p_xnH, (const uint32_t*)p_xnL,
        (const uint32_t*)p_wqkvH, (const uint32_t*)p_wqkvL,
        b_qkv, nullptr, nullptr, (float*)p_qkv, nullptr, nullptr, MM, 3072, Dd);
    // 4. rel-pos bias (+key mask folded in)
    relpos_k<<<dim3(Nseq, Bb), 128>>>(rel, w_rp1, b_rp1, w_rp2, b_rp2, mask);
    // 5. scores (tensor cores)
    scores_tc<<<dim3(8, 8, Bb * Hh), 128>>>();
    // 6. softmax
    softmax_k<<<(Bb * Hh * Nseq) / 8, 256>>>();
    // 7. P @ V (tensor cores) -> attn planes
    pv_tc<<<dim3(8, Bb * Hh), 128>>>();
    // 8. proj + residual with gate_s (chunk 2)
    gemm_tc<2><<<dim3(1024 / 128, MM / 128), 256>>>(
        (const uint32_t*)p_attnH, (const uint32_t*)p_attnL,
        (const uint32_t*)p_wprojH, (const uint32_t*)p_wprojL,
        b_proj, x, modf + 2 * Dd, (float*)p_x1, nullptr, nullptr, MM, Dd, Dd);
    // 9. LN2 + modulate -> xn planes
    ln_mod_k<<<MM, 256>>>((const float*)p_x1, g2, beta2, 3 * Dd, 4 * Dd,
                          (__nv_bfloat16*)p_xnH, (__nv_bfloat16*)p_xnL);
    // 10. fc1 + exact GELU -> hidden planes
    gemm_tc<1><<<dim3(HIDd / 128, MM / 128), 256>>>(
        (const uint32_t*)p_xnH, (const uint32_t*)p_xnL,
        (const uint32_t*)p_wfc1H, (const uint32_t*)p_wfc1L,
        b_fc1, nullptr, nullptr, nullptr, (uint32_t*)p_hH, (uint32_t*)p_hL, MM, HIDd, Dd);
    // 11. fc2 + residual with gate_m (chunk 5) -> final output
    gemm_tc<2><<<dim3(1024 / 128, MM / 128), 256>>>(
        (const uint32_t*)p_hH, (const uint32_t*)p_hL,
        (const uint32_t*)p_wfc2H, (const uint32_t*)p_wfc2L,
        b_fc2, (const float*)p_x1, modf + 5 * Dd, out, nullptr, nullptr, MM, Dd, HIDd);
}

// round 7
// speedup vs baseline: 2.2239x; 1.1404x over previous
#include <cuda_runtime.h>
#include <cuda_bf16.h>
#include <stdint.h>
#include <math.h>

// Problem constants
#define Bb   4
#define Nseq 512
#define Dd   1024
#define Hh   16
#define HDd  64
#define HIDd 4096
#define MM   (Bb * Nseq)     // 2048 rows
#define MODS (6 * Dd)        // 6144

// ---- scratch (no allocs allowed -> __device__ globals) ----
__device__ float g_mod[Bb * MODS];
__device__ float g_qkv[MM * 3 * Dd];
__device__ float g_bias[(size_t)Bb * Hh * Nseq * Nseq];
__device__ float g_scores[(size_t)Bb * Hh * Nseq * Nseq];
__device__ float g_x1[MM * Dd];

// hi/lo bf16 planes
__device__ __align__(16) __nv_bfloat16 g_xnH[MM * Dd];
__device__ __align__(16) __nv_bfloat16 g_xnL[MM * Dd];
__device__ uint32_t g_attnH[MM * Dd / 2];
__device__ uint32_t g_attnL[MM * Dd / 2];
__device__ uint32_t g_hH[(size_t)MM * HIDd / 2];
__device__ uint32_t g_hL[(size_t)MM * HIDd / 2];
// weight planes
__device__ uint32_t g_wqkvH[3 * Dd * Dd / 2];
__device__ uint32_t g_wqkvL[3 * Dd * Dd / 2];
__device__ uint32_t g_wprojH[Dd * Dd / 2];
__device__ uint32_t g_wprojL[Dd * Dd / 2];
__device__ uint32_t g_wfc1H[(size_t)HIDd * Dd / 2];
__device__ uint32_t g_wfc1L[(size_t)HIDd * Dd / 2];
__device__ uint32_t g_wfc2H[(size_t)Dd * HIDd / 2];
__device__ uint32_t g_wfc2L[(size_t)Dd * HIDd / 2];

__device__ __forceinline__ uint32_t pack_bf2(__nv_bfloat16 a, __nv_bfloat16 b) {
    unsigned short ua = *(unsigned short*)&a;
    unsigned short ub = *(unsigned short*)&b;
    return ((uint32_t)ub << 16) | ua;
}

__device__ __forceinline__ void split2(float x, float y, uint32_t& h, uint32_t& l) {
    __nv_bfloat16 hx = __float2bfloat16_rn(x);
    __nv_bfloat16 hy = __float2bfloat16_rn(y);
    __nv_bfloat16 lx = __float2bfloat16_rn(x - __bfloat162float(hx));
    __nv_bfloat16 ly = __float2bfloat16_rn(y - __bfloat162float(hy));
    h = pack_bf2(hx, hy);
    l = pack_bf2(lx, ly);
}

__device__ __forceinline__ void mma_bf16(float* c, const uint32_t* a, const uint32_t* b) {
    asm volatile(
        "mma.sync.aligned.m16n8k16.row.col.f32.bf16.bf16.f32 "
        "{%0,%1,%2,%3}, {%4,%5,%6,%7}, {%8,%9}, {%0,%1,%2,%3};"
        : "+f"(c[0]), "+f"(c[1]), "+f"(c[2]), "+f"(c[3])
        : "r"(a[0]), "r"(a[1]), "r"(a[2]), "r"(a[3]), "r"(b[0]), "r"(b[1]));
}

__device__ __forceinline__ void ldsm4(uint32_t& r0, uint32_t& r1, uint32_t& r2, uint32_t& r3,
                                      uint32_t addr) {
    asm volatile("ldmatrix.sync.aligned.m8n8.x4.shared.b16 {%0,%1,%2,%3}, [%4];"
                 : "=r"(r0), "=r"(r1), "=r"(r2), "=r"(r3) : "r"(addr));
}

__device__ __forceinline__ void cp16(uint32_t dst, const void* src) {
    asm volatile("cp.async.cg.shared.global [%0], [%1], 16;" :: "r"(dst), "l"(src));
}

// ============================================================
// 0) weight hi/lo split
// ============================================================
__global__ void cvtw_k(const float* __restrict__ src,
                       uint32_t* __restrict__ h, uint32_t* __restrict__ l) {
    int i = blockIdx.x * 256 + threadIdx.x;
    float2 v = ((const float2*)src)[i];
    uint32_t hh, ll;
    split2(v.x, v.y, hh, ll);
    h[i] = hh; l[i] = ll;
}

// ============================================================
// 1) adaLN
// ============================================================
__global__ void adaln_k(const float* __restrict__ t_emb,
                        const float* __restrict__ w,
                        const float* __restrict__ bias) {
    __shared__ float st[Dd];
    int b = blockIdx.y;
    for (int i = threadIdx.x; i < Dd; i += 256) {
        float t = t_emb[b * Dd + i];
        st[i] = t / (1.0f + expf(-t));
    }
    __syncthreads();
    int warp = threadIdx.x >> 5, lane = threadIdx.x & 31;
    int o = blockIdx.x * 8 + warp;
    const float* wr = w + (size_t)o * Dd;
    float acc = 0.0f;
    for (int k = lane; k < Dd; k += 32) acc = fmaf(st[k], wr[k], acc);
    #pragma unroll
    for (int s = 16; s; s >>= 1) acc += __shfl_xor_sync(0xffffffff, acc, s);
    if (lane == 0) g_mod[b * MODS + o] = acc + bias[o];
}

// ============================================================
// 2) LayerNorm + modulate -> hi/lo planes
// ============================================================
__global__ void ln_mod_k(const float* __restrict__ x,
                         const float* __restrict__ g,
                         const float* __restrict__ beta,
                         int shiftOff, int scaleOff,
                         __nv_bfloat16* __restrict__ outH,
                         __nv_bfloat16* __restrict__ outL) {
    int row = blockIdx.x;
    int b = row >> 9;
    const float* xr = x + (size_t)row * Dd;
    __shared__ float r1[256], r2[256];
    float s = 0.0f, s2 = 0.0f;
    for (int j = threadIdx.x; j < Dd; j += 256) {
        float v = xr[j];
        s += v; s2 = fmaf(v, v, s2);
    }
    r1[threadIdx.x] = s; r2[threadIdx.x] = s2;
    __syncthreads();
    for (int st = 128; st; st >>= 1) {
        if (threadIdx.x < st) {
            r1[threadIdx.x] += r1[threadIdx.x + st];
            r2[threadIdx.x] += r2[threadIdx.x + st];
        }
        __syncthreads();
    }
    float mu = r1[0] * (1.0f / Dd);
    float var = r2[0] * (1.0f / Dd) - mu * mu;
    float rstd = rsqrtf(var + 1e-5f);
    const float* sh = g_mod + b * MODS + shiftOff;
    const float* sc = g_mod + b * MODS + scaleOff;
    __nv_bfloat16* oh = outH + (size_t)row * Dd;
    __nv_bfloat16* ol = outL + (size_t)row * Dd;
    for (int j = threadIdx.x; j < Dd; j += 256) {
        float v = (xr[j] - mu) * rstd * g[j] + beta[j];
        float m = fmaf(v, 1.0f + sc[j], sh[j]);
        __nv_bfloat16 h = __float2bfloat16_rn(m);
        oh[j] = h;
        ol[j] = __float2bfloat16_rn(m - __bfloat162float(h));
    }
}

// ============================================================
// 3) Tensor-core NT GEMM, cp.async double-buffered + ldmatrix.
//    Block 128x128x32, 8 warps, warp tile 64x32.
//    Dynamic smem: 2 stages x (AH|AL|BH|BL) x 128 x 40 bf16.
// ============================================================
#define SPITCH 40           // bf16 elems per row (80B pitch)
#define ARR_BYTES 10240     // 128*40*2
#define STG_BYTES 40960     // 4 arrays
#define SMEM_DYN  81920     // 2 stages

template <int EPI>
__global__ void __launch_bounds__(256, 2)
gemm_tc(const uint32_t* __restrict__ AH, const uint32_t* __restrict__ AL,
        const uint32_t* __restrict__ BH, const uint32_t* __restrict__ BL,
        const float* __restrict__ bias, const float* __restrict__ res,
        const float* __restrict__ gate, float* __restrict__ C,
        uint32_t* __restrict__ CH, uint32_t* __restrict__ CL,
        int M, int N, int K) {
    extern __shared__ char smdyn[];
    uint32_t sbase = (uint32_t)__cvta_generic_to_shared(smdyn);

    int bm = blockIdx.y * 128, bn = blockIdx.x * 128;
    int tid = threadIdx.x;
    int warp = tid >> 5, lane = tid & 31;
    int wm = warp >> 2, wn = warp & 3;
    int mi = lane >> 3, rr = lane & 7;

    // ldmatrix per-lane byte offsets
    uint32_t offA[4], offB[2];
    #pragma unroll
    for (int mt = 0; mt < 4; mt++) {
        int row = wm * 64 + mt * 16 + (mi & 1) * 8 + rr;
        int col = (mi >> 1) * 8;
        offA[mt] = (uint32_t)(row * SPITCH + col) * 2;
    }
    #pragma unroll
    for (int p = 0; p < 2; p++) {
        int row = wn * 32 + p * 16 + (mi >> 1) * 8 + rr;
        int col = (mi & 1) * 8;
        offB[p] = (uint32_t)(row * SPITCH + col) * 2;
    }

    // staging: each thread copies 2 x 16B per array
    int lr = tid >> 1, kofe = (tid & 1) * 16, kofu = (tid & 1) * 8;
    uint32_t stoff = (uint32_t)(lr * SPITCH + kofe) * 2;

    int K2 = K >> 1;
    const uint32_t* AHp = AH + (size_t)(bm + lr) * K2 + kofu;
    const uint32_t* ALp = AL + (size_t)(bm + lr) * K2 + kofu;
    const uint32_t* BHp = BH + (size_t)(bn + lr) * K2 + kofu;
    const uint32_t* BLp = BL + (size_t)(bn + lr) * K2 + kofu;

    float acc[4][4][4] = {};
    int NIT = K2 >> 4;  // 16 u32 (32 elems) per stage

    // prologue: stage 0
    {
        uint32_t d = sbase + stoff;
        cp16(d,                  AHp);     cp16(d + 16,                  AHp + 4);
        cp16(d + ARR_BYTES,      ALp);     cp16(d + ARR_BYTES + 16,      ALp + 4);
        cp16(d + 2 * ARR_BYTES,  BHp);     cp16(d + 2 * ARR_BYTES + 16,  BHp + 4);
        cp16(d + 3 * ARR_BYTES,  BLp);     cp16(d + 3 * ARR_BYTES + 16,  BLp + 4);
    }
    asm volatile("cp.async.commit_group;");

    for (int it = 0; it < NIT; it++) {
        int s = it & 1;
        if (it + 1 < NIT) {
            int k0 = (it + 1) << 4;
            uint32_t d = sbase + (s ^ 1) * STG_BYTES + stoff;
            cp16(d,                  AHp + k0);     cp16(d + 16,                  AHp + k0 + 4);
            cp16(d + ARR_BYTES,      ALp + k0);     cp16(d + ARR_BYTES + 16,      ALp + k0 + 4);
            cp16(d + 2 * ARR_BYTES,  BHp + k0);     cp16(d + 2 * ARR_BYTES + 16,  BHp + k0 + 4);
            cp16(d + 3 * ARR_BYTES,  BLp + k0);     cp16(d + 3 * ARR_BYTES + 16,  BLp + k0 + 4);
        }
        asm volatile("cp.async.commit_group;");
        asm volatile("cp.async.wait_group 1;");
        __syncthreads();

        uint32_t sb = sbase + s * STG_BYTES;
        #pragma unroll
        for (int kkb = 0; kkb < 64; kkb += 32) {   // 2 x k16 (byte offset)
            uint32_t aH[4][4], aL[4][4];
            #pragma unroll
            for (int mt = 0; mt < 4; mt++) {
                ldsm4(aH[mt][0], aH[mt][1], aH[mt][2], aH[mt][3],
                      sb + offA[mt] + kkb);
                ldsm4(aL[mt][0], aL[mt][1], aL[mt][2], aL[mt][3],
                      sb + ARR_BYTES + offA[mt] + kkb);
            }
            #pragma unroll
            for (int p = 0; p < 2; p++) {
                uint32_t bH[4], bL[4];
                ldsm4(bH[0], bH[1], bH[2], bH[3], sb + 2 * ARR_BYTES + offB[p] + kkb);
                ldsm4(bL[0], bL[1], bL[2], bL[3], sb + 3 * ARR_BYTES + offB[p] + kkb);
                #pragma unroll
                for (int mt = 0; mt < 4; mt++) {
                    mma_bf16(acc[mt][2 * p],     aH[mt], bH);
                    mma_bf16(acc[mt][2 * p],     aH[mt], bL);
                    mma_bf16(acc[mt][2 * p],     aL[mt], bH);
                    mma_bf16(acc[mt][2 * p + 1], aH[mt], bH + 2);
                    mma_bf16(acc[mt][2 * p + 1], aH[mt], bL + 2);
                    mma_bf16(acc[mt][2 * p + 1], aL[mt], bH + 2);
                }
            }
        }
        __syncthreads();
    }

    // ---- epilogue ----
    int g = lane >> 2, tig = lane & 3;
    #pragma unroll
    for (int mt = 0; mt < 4; mt++) {
        #pragma unroll
        for (int rrv = 0; rrv < 2; rrv++) {
            int r = bm + wm * 64 + mt * 16 + g + rrv * 8;
            int bb = r >> 9;
            #pragma unroll
            for (int nt = 0; nt < 4; nt++) {
                int c = bn + wn * 32 + nt * 8 + 2 * tig;
                float v0 = acc[mt][nt][rrv * 2 + 0] + bias[c];
                float v1 = acc[mt][nt][rrv * 2 + 1] + bias[c + 1];
                size_t off = (size_t)r * N + c;
                if (EPI == 1) {
                    v0 = v0 * normcdff(v0);
                    v1 = v1 * normcdff(v1);
                    uint32_t hh, ll;
                    split2(v0, v1, hh, ll);
                    CH[off >> 1] = hh; CL[off >> 1] = ll;
                } else {
                    if (EPI == 2) {
                        v0 = res[off]     + gate[bb * MODS + c]     * v0;
                        v1 = res[off + 1] + gate[bb * MODS + c + 1] * v1;
                    }
                    *(float2*)(C + off) = make_float2(v0, v1);
                }
            }
        }
    }
}

// ============================================================
// 4) Rel-pos bias MLP
// ============================================================
__global__ void __launch_bounds__(128)
relpos_k(const float* __restrict__ rel,
         const float* __restrict__ w1, const float* __restrict__ b1,
         const float* __restrict__ w2, const float* __restrict__ b2,
         const int* __restrict__ mask) {
    __shared__ float W1[128], B1[64], W2T[64][16], B2s[16];
    int tid = threadIdx.x;
    if (tid < 128) W1[tid] = w1[tid];
    if (tid < 64)  B1[tid] = b1[tid];
    for (int i = tid; i < 1024; i += 128) {
        int j = i >> 4, t = i & 15;
        W2T[j][t] = w2[t * 64 + j];
    }
    if (tid < 16)  B2s[tid] = b2[tid];
    __syncthreads();
    int b = blockIdx.y, n = blockIdx.x;
    const float* rbase = rel + ((size_t)(b * Nseq + n) * Nseq) * 2;
    float2 r[4]; bool ok[4];
    #pragma unroll
    for (int i = 0; i < 4; i++) {
        int m = tid + 128 * i;
        r[i] = *(const float2*)(rbase + 2 * m);
        ok[i] = (mask[b * Nseq + m] != 0);
    }
    float out[4][16];
    #pragma unroll
    for (int i = 0; i < 4; i++)
        #pragma unroll
        for (int t = 0; t < 16; t++) out[i][t] = B2s[t];
    #pragma unroll 8
    for (int j = 0; j < 64; j++) {
        float w1x = W1[2 * j], w1y = W1[2 * j + 1], bb = B1[j];
        float hj[4];
        #pragma unroll
        for (int i = 0; i < 4; i++)
            hj[i] = fmaxf(fmaf(w1x, r[i].x, fmaf(w1y, r[i].y, bb)), 0.0f);
        float4 w0 = *(const float4*)&W2T[j][0];
        float4 w4 = *(const float4*)&W2T[j][4];
        float4 w8 = *(const float4*)&W2T[j][8];
        float4 wc = *(const float4*)&W2T[j][12];
        float wv[16] = {w0.x, w0.y, w0.z, w0.w, w4.x, w4.y, w4.z, w4.w,
                        w8.x, w8.y, w8.z, w8.w, wc.x, wc.y, wc.z, wc.w};
        #pragma unroll
        for (int i = 0; i < 4; i++)
            #pragma unroll
            for (int t = 0; t < 16; t++)
                out[i][t] = fmaf(wv[t], hj[i], out[i][t]);
    }
    #pragma unroll
    for (int t = 0; t < 16; t++) {
        #pragma unroll
        for (int i = 0; i < 4; i++) {
            int m = tid + 128 * i;
            size_t idx = (((size_t)(b * Hh + t) * Nseq) + n) * Nseq + m;
            g_bias[idx] = ok[i] ? out[i][t] : -INFINITY;
        }
    }
}

// ============================================================
// 5) Attention scores via tensor cores
// ============================================================
__global__ void __launch_bounds__(128)
scores_tc() {
    __shared__ __nv_bfloat16 QH[64][72], QL[64][72], KH[64][72], KL[64][72];
    int bh = blockIdx.z, b = bh >> 4, h = bh & 15;
    int n0 = blockIdx.y * 64, m0 = blockIdx.x * 64;
    int tid = threadIdx.x;
    int warp = tid >> 5, lane = tid & 31;
    int g = lane >> 2, tig = lane & 3;
    int srow = tid >> 1, kof = (tid & 1) * 32;

    const float* qb = g_qkv + (size_t)(b * Nseq + n0 + srow) * 3072 + h * 64 + kof;
    const float* kb = g_qkv + (size_t)(b * Nseq + m0 + srow) * 3072 + 1024 + h * 64 + kof;
    #pragma unroll
    for (int q = 0; q < 8; q++) {
        float4 v = ((const float4*)qb)[q];
        uint32_t h0, l0, h1, l1;
        split2(v.x, v.y, h0, l0);
        split2(v.z, v.w, h1, l1);
        *(uint32_t*)&QH[srow][kof + q * 4]     = h0;
        *(uint32_t*)&QH[srow][kof + q * 4 + 2] = h1;
        *(uint32_t*)&QL[srow][kof + q * 4]     = l0;
        *(uint32_t*)&QL[srow][kof + q * 4 + 2] = l1;
        float4 w = ((const float4*)kb)[q];
        split2(w.x, w.y, h0, l0);
        split2(w.z, w.w, h1, l1);
        *(uint32_t*)&KH[srow][kof + q * 4]     = h0;
        *(uint32_t*)&KH[srow][kof + q * 4 + 2] = h1;
        *(uint32_t*)&KL[srow][kof + q * 4]     = l0;
        *(uint32_t*)&KL[srow][kof + q * 4 + 2] = l1;
    }
    __syncthreads();

    float acc[8][4] = {};
    #pragma unroll
    for (int kk = 0; kk < 64; kk += 16) {
        uint32_t aH[4], aL[4];
        int r0 = warp * 16 + g;
        aH[0] = *(uint32_t*)&QH[r0][kk + 2 * tig];
        aH[1] = *(uint32_t*)&QH[r0 + 8][kk + 2 * tig];
        aH[2] = *(uint32_t*)&QH[r0][kk + 2 * tig + 8];
        aH[3] = *(uint32_t*)&QH[r0 + 8][kk + 2 * tig + 8];
        aL[0] = *(uint32_t*)&QL[r0][kk + 2 * tig];
        aL[1] = *(uint32_t*)&QL[r0 + 8][kk + 2 * tig];
        aL[2] = *(uint32_t*)&QL[r0][kk + 2 * tig + 8];
        aL[3] = *(uint32_t*)&QL[r0 + 8][kk + 2 * tig + 8];
        #pragma unroll
        for (int nt = 0; nt < 8; nt++) {
            int c0 = nt * 8 + g;
            uint32_t bH[2], bL[2];
            bH[0] = *(uint32_t*)&KH[c0][kk + 2 * tig];
            bH[1] = *(uint32_t*)&KH[c0][kk + 2 * tig + 8];
            bL[0] = *(uint32_t*)&KL[c0][kk + 2 * tig];
            bL[1] = *(uint32_t*)&KL[c0][kk + 2 * tig + 8];
            mma_bf16(acc[nt], aH, bH);
            mma_bf16(acc[nt], aH, bL);
            mma_bf16(acc[nt], aL, bH);
        }
    }
    #pragma unroll
    for (int nt = 0; nt < 8; nt++) {
        #pragma unroll
        for (int rr = 0; rr < 2; rr++) {
            int n = n0 + warp * 16 + g + rr * 8;
            int m = m0 + nt * 8 + 2 * tig;
            size_t idx = ((size_t)bh * Nseq + n) * Nseq + m;
            float2 bv = *(const float2*)&g_bias[idx];
            float2 o;
            o.x = fmaf(acc[nt][rr * 2 + 0], 0.125f, bv.x);
            o.y = fmaf(acc[nt][rr * 2 + 1], 0.125f, bv.y);
            *(float2*)&g_scores[idx] = o;
        }
    }
}

// ============================================================
// 6) Row softmax
// ============================================================
__global__ void softmax_k() {
    int row = blockIdx.x * 8 + (threadIdx.x >> 5);
    int lane = threadIdx.x & 31;
    float* p = g_scores + (size_t)row * Nseq;
    float vals[16];
    float mx = -INFINITY;
    #pragma unroll
    for (int i = 0; i < 16; i++) { vals[i] = p[lane + i * 32]; mx = fmaxf(mx, vals[i]); }
    #pragma unroll
    for (int s = 16; s; s >>= 1) mx = fmaxf(mx, __shfl_xor_sync(0xffffffff, mx, s));
    float sum = 0.0f;
    #pragma unroll
    for (int i = 0; i < 16; i++) { vals[i] = __expf(vals[i] - mx); sum += vals[i]; }
    #pragma unroll
    for (int s = 16; s; s >>= 1) sum += __shfl_xor_sync(0xffffffff, sum, s);
    float inv = 1.0f / sum;
    #pragma unroll
    for (int i = 0; i < 16; i++) p[lane + i * 32] = vals[i] * inv;
}

// ============================================================
// 7) P @ V via tensor cores -> attn hi/lo planes
// ============================================================
__global__ void __launch_bounds__(128)
pv_tc() {
    __shared__ __align__(16) unsigned char su[2 * 64 * 72 * 2];
    float (*Vs)[68] = (float(*)[68])su;
    __nv_bfloat16 (*PH)[72] = (__nv_bfloat16(*)[72])su;
    __nv_bfloat16 (*PL)[72] = (__nv_bfloat16(*)[72])(su + 64 * 72 * 2);
    __shared__ __nv_bfloat16 VtH[64][72], VtL[64][72];

    int bh = blockIdx.y, b = bh >> 4, h = bh & 15;
    int n0 = blockIdx.x * 64;
    int tid = threadIdx.x;
    int warp = tid >> 5, lane = tid & 31;
    int g = lane >> 2, tig = lane & 3;
    int srow = tid >> 1, kof = (tid & 1) * 32;
    int dcol = tid & 63, mh = (tid >> 6) * 32;

    float acc[8][4] = {};

    for (int m0 = 0; m0 < Nseq; m0 += 64) {
        __syncthreads();
        const float* vb = g_qkv + (size_t)(b * Nseq + m0 + srow) * 3072 + 2048 + h * 64 + kof;
        #pragma unroll
        for (int q = 0; q < 8; q++)
            *(float4*)&Vs[srow][kof + q * 4] = ((const float4*)vb)[q];
        __syncthreads();
        {
            float tv[32];
            #pragma unroll
            for (int j = 0; j < 32; j++) tv[j] = Vs[mh + j][dcol];
            #pragma unroll
            for (int e = 0; e < 16; e++) {
                uint32_t hh, ll;
                split2(tv[2 * e], tv[2 * e + 1], hh, ll);
                *(uint32_t*)&VtH[dcol][mh + 2 * e] = hh;
                *(uint32_t*)&VtL[dcol][mh + 2 * e] = ll;
            }
        }
        __syncthreads();
        const float* pb = g_scores + ((size_t)bh * Nseq + n0 + srow) * Nseq + m0 + kof;
        #pragma unroll
        for (int q = 0; q < 8; q++) {
            float4 v = ((const float4*)pb)[q];
            uint32_t h0, l0, h1, l1;
            split2(v.x, v.y, h0, l0);
            split2(v.z, v.w, h1, l1);
            *(uint32_t*)&PH[srow][kof + q * 4]     = h0;
            *(uint32_t*)&PH[srow][kof + q * 4 + 2] = h1;
            *(uint32_t*)&PL[srow][kof + q * 4]     = l0;
            *(uint32_t*)&PL[srow][kof + q * 4 + 2] = l1;
        }
        __syncthreads();
        #pragma unroll
        for (int kk = 0; kk < 64; kk += 16) {
            uint32_t aH[4], aL[4];
            int r0 = warp * 16 + g;
            aH[0] = *(uint32_t*)&PH[r0][kk + 2 * tig];
            aH[1] = *(uint32_t*)&PH[r0 + 8][kk + 2 * tig];
            aH[2] = *(uint32_t*)&PH[r0][kk + 2 * tig + 8];
            aH[3] = *(uint32_t*)&PH[r0 + 8][kk + 2 * tig + 8];
            aL[0] = *(uint32_t*)&PL[r0][kk + 2 * tig];
            aL[1] = *(uint32_t*)&PL[r0 + 8][kk + 2 * tig];
            aL[2] = *(uint32_t*)&PL[r0][kk + 2 * tig + 8];
            aL[3] = *(uint32_t*)&PL[r0 + 8][kk + 2 * tig + 8];
            #pragma unroll
            for (int nt = 0; nt < 8; nt++) {
                int c0 = nt * 8 + g;
                uint32_t bH[2], bL[2];
                bH[0] = *(uint32_t*)&VtH[c0][kk + 2 * tig];
                bH[1] = *(uint32_t*)&VtH[c0][kk + 2 * tig + 8];
                bL[0] = *(uint32_t*)&VtL[c0][kk + 2 * tig];
                bL[1] = *(uint32_t*)&VtL[c0][kk + 2 * tig + 8];
                mma_bf16(acc[nt], aH, bH);
                mma_bf16(acc[nt], aH, bL);
                mma_bf16(acc[nt], aL, bH);
            }
        }
    }
    #pragma unroll
    for (int nt = 0; nt < 8; nt++) {
        #pragma unroll
        for (int rr = 0; rr < 2; rr++) {
            int n = n0 + warp * 16 + g + rr * 8;
            int d = nt * 8 + 2 * tig;
            uint32_t hh, ll;
            split2(acc[nt][rr * 2 + 0], acc[nt][rr * 2 + 1], hh, ll);
            size_t off2 = ((size_t)(b * Nseq + n) * Dd + h * 64 + d) >> 1;
            g_attnH[off2] = hh;
            g_attnL[off2] = ll;
        }
    }
}

// ============================================================
// host-side launcher
// ============================================================
extern "C" void kernel_launch(void* const* d_in, const int* in_sizes, int n_in,
                              void* d_out, int out_size) {
    const float* x      = (const float*)d_in[0];
    const float* t_emb  = (const float*)d_in[1];
    const float* rel    = (const float*)d_in[2];
    const int*   mask   = (const int*)d_in[3];
    const float* w_ada  = (const float*)d_in[4];
    const float* b_ada  = (const float*)d_in[5];
    const float* g1     = (const float*)d_in[6];
    const float* beta1  = (const float*)d_in[7];
    const float* g2     = (const float*)d_in[8];
    const float* beta2  = (const float*)d_in[9];
    const float* w_qkv  = (const float*)d_in[10];
    const float* b_qkv  = (const float*)d_in[11];
    const float* w_proj = (const float*)d_in[12];
    const float* b_proj = (const float*)d_in[13];
    const float* w_rp1  = (const float*)d_in[14];
    const float* b_rp1  = (const float*)d_in[15];
    const float* w_rp2  = (const float*)d_in[16];
    const float* b_rp2  = (const float*)d_in[17];
    const float* w_fc1  = (const float*)d_in[18];
    const float* b_fc1  = (const float*)d_in[19];
    const float* w_fc2  = (const float*)d_in[20];
    const float* b_fc2  = (const float*)d_in[21];
    float* out = (float*)d_out;

    void *p_mod, *p_qkv, *p_x1;
    void *p_xnH, *p_xnL, *p_attnH, *p_attnL, *p_hH, *p_hL;
    void *p_wqkvH, *p_wqkvL, *p_wprojH, *p_wprojL, *p_wfc1H, *p_wfc1L, *p_wfc2H, *p_wfc2L;
    cudaGetSymbolAddress(&p_mod,  g_mod);
    cudaGetSymbolAddress(&p_qkv,  g_qkv);
    cudaGetSymbolAddress(&p_x1,   g_x1);
    cudaGetSymbolAddress(&p_xnH,  g_xnH);
    cudaGetSymbolAddress(&p_xnL,  g_xnL);
    cudaGetSymbolAddress(&p_attnH, g_attnH);
    cudaGetSymbolAddress(&p_attnL, g_attnL);
    cudaGetSymbolAddress(&p_hH,   g_hH);
    cudaGetSymbolAddress(&p_hL,   g_hL);
    cudaGetSymbolAddress(&p_wqkvH, g_wqkvH);
    cudaGetSymbolAddress(&p_wqkvL, g_wqkvL);
    cudaGetSymbolAddress(&p_wprojH, g_wprojH);
    cudaGetSymbolAddress(&p_wprojL, g_wprojL);
    cudaGetSymbolAddress(&p_wfc1H, g_wfc1H);
    cudaGetSymbolAddress(&p_wfc1L, g_wfc1L);
    cudaGetSymbolAddress(&p_wfc2H, g_wfc2H);
    cudaGetSymbolAddress(&p_wfc2L, g_wfc2L);
    float* modf = (float*)p_mod;

    cudaFuncSetAttribute(gemm_tc<0>, cudaFuncAttributeMaxDynamicSharedMemorySize, SMEM_DYN);
    cudaFuncSetAttribute(gemm_tc<1>, cudaFuncAttributeMaxDynamicSharedMemorySize, SMEM_DYN);
    cudaFuncSetAttribute(gemm_tc<2>, cudaFuncAttributeMaxDynamicSharedMemorySize, SMEM_DYN);

    // 0. weight hi/lo planes
    cvtw_k<<<(3 * Dd * Dd / 2) / 256, 256>>>(w_qkv, (uint32_t*)p_wqkvH, (uint32_t*)p_wqkvL);
    cvtw_k<<<(Dd * Dd / 2) / 256, 256>>>(w_proj, (uint32_t*)p_wprojH, (uint32_t*)p_wprojL);
    cvtw_k<<<(HIDd * Dd / 2) / 256, 256>>>(w_fc1, (uint32_t*)p_wfc1H, (uint32_t*)p_wfc1L);
    cvtw_k<<<(Dd * HIDd / 2) / 256, 256>>>(w_fc2, (uint32_t*)p_wfc2H, (uint32_t*)p_wfc2L);
    // 1. adaLN modulation
    adaln_k<<<dim3(768, 4), 256>>>(t_emb, w_ada, b_ada);
    // 2. LN1 + modulate -> xn planes
    ln_mod_k<<<MM, 256>>>(x, g1, beta1, 0, Dd,
                          (__nv_bfloat16*)p_xnH, (__nv_bfloat16*)p_xnL);
    // 3. QKV projection
    gemm_tc<0><<<dim3(3072 / 128, MM / 128), 256, SMEM_DYN>>>(
        (const uint32_t*)p_xnH, (const uint32_t*)p_xnL,
        (const uint32_t*)p_wqkvH, (const uint32_t*)p_wqkvL,
        b_qkv, nullptr, nullptr, (float*)p_qkv, nullptr, nullptr, MM, 3072, Dd);
    // 4. rel-pos bias
    relpos_k<<<dim3(Nseq, Bb), 128>>>(rel, w_rp1, b_rp1, w_rp2, b_rp2, mask);
    // 5. scores
    scores_tc<<<dim3(8, 8, Bb * Hh), 128>>>();
    // 6. softmax
    softmax_k<<<(Bb * Hh * Nseq) / 8, 256>>>();
    // 7. P @ V
    pv_tc<<<dim3(8, Bb * Hh), 128>>>();
    // 8. proj + residual gate_s
    gemm_tc<2><<<dim3(1024 / 128, MM / 128), 256, SMEM_DYN>>>(
        (const uint32_t*)p_attnH, (const uint32_t*)p_attnL,
        (const uint32_t*)p_wprojH, (const uint32_t*)p_wprojL,
        b_proj, x, modf + 2 * Dd, (float*)p_x1, nullptr, nullptr, MM, Dd, Dd);
    // 9. LN2 + modulate -> xn planes
    ln_mod_k<<<MM, 256>>>((const float*)p_x1, g2, beta2, 3 * Dd, 4 * Dd,
                          (__nv_bfloat16*)p_xnH, (__nv_bfloat16*)p_xnL);
    // 10. fc1 + GELU -> hidden planes
    gemm_tc<1><<<dim3(HIDd / 128, MM / 128), 256, SMEM_DYN>>>(
        (const uint32_t*)p_xnH, (const uint32_t*)p_xnL,
        (const uint32_t*)p_wfc1H, (const uint32_t*)p_wfc1L,
        b_fc1, nullptr, nullptr, nullptr, (uint32_t*)p_hH, (uint32_t*)p_hL, MM, HIDd, Dd);
    // 11. fc2 + residual gate_m -> final output
    gemm_tc<2><<<dim3(1024 / 128, MM / 128), 256, SMEM_DYN>>>(
        (const uint32_t*)p_hH, (const uint32_t*)p_hL,
        (const uint32_t*)p_wfc2H, (const uint32_t*)p_wfc2L,
        b_fc2, (const float*)p_x1, modf + 5 * Dd, out, nullptr, nullptr, MM, Dd, HIDd);
}

// round 11
// speedup vs baseline: 2.4817x; 1.1159x over previous
#include <cuda_runtime.h>
#include <cuda_bf16.h>
#include <stdint.h>
#include <math.h>

// Problem constants
#define Bb   4
#define Nseq 512
#define Dd   1024
#define Hh   16
#define HDd  64
#define HIDd 4096
#define MM   (Bb * Nseq)     // 2048 rows
#define MODS (6 * Dd)        // 6144

// ---- scratch ----
__device__ float g_mod[Bb * MODS];
__device__ float g_qkv[MM * 3 * Dd];
__device__ float g_bias[(size_t)Bb * Hh * Nseq * Nseq];
__device__ float g_x1[MM * Dd];

// hi/lo bf16 planes
__device__ __align__(16) __nv_bfloat16 g_xnH[MM * Dd];
__device__ __align__(16) __nv_bfloat16 g_xnL[MM * Dd];
__device__ uint32_t g_attnH[MM * Dd / 2];
__device__ uint32_t g_attnL[MM * Dd / 2];
__device__ uint32_t g_hH[(size_t)MM * HIDd / 2];
__device__ uint32_t g_hL[(size_t)MM * HIDd / 2];
// weight planes
__device__ uint32_t g_wqkvH[3 * Dd * Dd / 2];
__device__ uint32_t g_wqkvL[3 * Dd * Dd / 2];
__device__ uint32_t g_wprojH[Dd * Dd / 2];
__device__ uint32_t g_wprojL[Dd * Dd / 2];
__device__ uint32_t g_wfc1H[(size_t)HIDd * Dd / 2];
__device__ uint32_t g_wfc1L[(size_t)HIDd * Dd / 2];
__device__ uint32_t g_wfc2H[(size_t)Dd * HIDd / 2];
__device__ uint32_t g_wfc2L[(size_t)Dd * HIDd / 2];

__device__ __forceinline__ uint32_t pack_bf2(__nv_bfloat16 a, __nv_bfloat16 b) {
    unsigned short ua = *(unsigned short*)&a;
    unsigned short ub = *(unsigned short*)&b;
    return ((uint32_t)ub << 16) | ua;
}

__device__ __forceinline__ void split2(float x, float y, uint32_t& h, uint32_t& l) {
    __nv_bfloat16 hx = __float2bfloat16_rn(x);
    __nv_bfloat16 hy = __float2bfloat16_rn(y);
    __nv_bfloat16 lx = __float2bfloat16_rn(x - __bfloat162float(hx));
    __nv_bfloat16 ly = __float2bfloat16_rn(y - __bfloat162float(hy));
    h = pack_bf2(hx, hy);
    l = pack_bf2(lx, ly);
}

__device__ __forceinline__ void mma_bf16(float* c, const uint32_t* a, const uint32_t* b) {
    asm volatile(
        "mma.sync.aligned.m16n8k16.row.col.f32.bf16.bf16.f32 "
        "{%0,%1,%2,%3}, {%4,%5,%6,%7}, {%8,%9}, {%0,%1,%2,%3};"
        : "+f"(c[0]), "+f"(c[1]), "+f"(c[2]), "+f"(c[3])
        : "r"(a[0]), "r"(a[1]), "r"(a[2]), "r"(a[3]), "r"(b[0]), "r"(b[1]));
}

__device__ __forceinline__ void ldsm4(uint32_t& r0, uint32_t& r1, uint32_t& r2, uint32_t& r3,
                                      uint32_t addr) {
    asm volatile("ldmatrix.sync.aligned.m8n8.x4.shared.b16 {%0,%1,%2,%3}, [%4];"
                 : "=r"(r0), "=r"(r1), "=r"(r2), "=r"(r3) : "r"(addr));
}

__device__ __forceinline__ void cp16(uint32_t dst, const void* src) {
    asm volatile("cp.async.cg.shared.global [%0], [%1], 16;" :: "r"(dst), "l"(src));
}

// ============================================================
// 0) weight hi/lo split (float4 vectorized)
// ============================================================
__global__ void cvtw_k(const float4* __restrict__ src,
                       uint2* __restrict__ h, uint2* __restrict__ l) {
    int i = blockIdx.x * 256 + threadIdx.x;
    float4 v = src[i];
    uint32_t h0, l0, h1, l1;
    split2(v.x, v.y, h0, l0);
    split2(v.z, v.w, h1, l1);
    h[i] = make_uint2(h0, h1);
    l[i] = make_uint2(l0, l1);
}

// ============================================================
// 1) adaLN
// ============================================================
__global__ void adaln_k(const float* __restrict__ t_emb,
                        const float* __restrict__ w,
                        const float* __restrict__ bias) {
    __shared__ float st[Dd];
    int b = blockIdx.y;
    for (int i = threadIdx.x; i < Dd; i += 256) {
        float t = t_emb[b * Dd + i];
        st[i] = t / (1.0f + expf(-t));
    }
    __syncthreads();
    int warp = threadIdx.x >> 5, lane = threadIdx.x & 31;
    int o = blockIdx.x * 8 + warp;
    const float* wr = w + (size_t)o * Dd;
    float acc = 0.0f;
    for (int k = lane; k < Dd; k += 32) acc = fmaf(st[k], wr[k], acc);
    #pragma unroll
    for (int s = 16; s; s >>= 1) acc += __shfl_xor_sync(0xffffffff, acc, s);
    if (lane == 0) g_mod[b * MODS + o] = acc + bias[o];
}

// ============================================================
// 2) LayerNorm + modulate -> hi/lo planes
// ============================================================
__global__ void ln_mod_k(const float* __restrict__ x,
                         const float* __restrict__ g,
                         const float* __restrict__ beta,
                         int shiftOff, int scaleOff,
                         __nv_bfloat16* __restrict__ outH,
                         __nv_bfloat16* __restrict__ outL) {
    int row = blockIdx.x;
    int b = row >> 9;
    const float* xr = x + (size_t)row * Dd;
    __shared__ float r1[256], r2[256];
    float s = 0.0f, s2 = 0.0f;
    for (int j = threadIdx.x; j < Dd; j += 256) {
        float v = xr[j];
        s += v; s2 = fmaf(v, v, s2);
    }
    r1[threadIdx.x] = s; r2[threadIdx.x] = s2;
    __syncthreads();
    for (int st = 128; st; st >>= 1) {
        if (threadIdx.x < st) {
            r1[threadIdx.x] += r1[threadIdx.x + st];
            r2[threadIdx.x] += r2[threadIdx.x + st];
        }
        __syncthreads();
    }
    float mu = r1[0] * (1.0f / Dd);
    float var = r2[0] * (1.0f / Dd) - mu * mu;
    float rstd = rsqrtf(var + 1e-5f);
    const float* sh = g_mod + b * MODS + shiftOff;
    const float* sc = g_mod + b * MODS + scaleOff;
    __nv_bfloat16* oh = outH + (size_t)row * Dd;
    __nv_bfloat16* ol = outL + (size_t)row * Dd;
    for (int j = threadIdx.x; j < Dd; j += 256) {
        float v = (xr[j] - mu) * rstd * g[j] + beta[j];
        float m = fmaf(v, 1.0f + sc[j], sh[j]);
        __nv_bfloat16 h = __float2bfloat16_rn(m);
        oh[j] = h;
        ol[j] = __float2bfloat16_rn(m - __bfloat162float(h));
    }
}

// ============================================================
// 3) Tensor-core NT GEMM, cp.async double-buffered + ldmatrix.
// ============================================================
#define SPITCH 40           // bf16 elems per row (80B pitch)
#define ARR_BYTES 10240     // 128*40*2
#define STG_BYTES 40960     // 4 arrays
#define SMEM_DYN  81920     // 2 stages

template <int EPI>
__global__ void __launch_bounds__(256, 2)
gemm_tc(const uint32_t* __restrict__ AH, const uint32_t* __restrict__ AL,
        const uint32_t* __restrict__ BH, const uint32_t* __restrict__ BL,
        const float* __restrict__ bias, const float* __restrict__ res,
        const float* __restrict__ gate, float* __restrict__ C,
        uint32_t* __restrict__ CH, uint32_t* __restrict__ CL,
        int M, int N, int K) {
    extern __shared__ char smdyn[];
    uint32_t sbase = (uint32_t)__cvta_generic_to_shared(smdyn);

    int bm = blockIdx.y * 128, bn = blockIdx.x * 128;
    int tid = threadIdx.x;
    int warp = tid >> 5, lane = tid & 31;
    int wm = warp >> 2, wn = warp & 3;
    int mi = lane >> 3, rr = lane & 7;

    uint32_t offA[4], offB[2];
    #pragma unroll
    for (int mt = 0; mt < 4; mt++) {
        int row = wm * 64 + mt * 16 + (mi & 1) * 8 + rr;
        int col = (mi >> 1) * 8;
        offA[mt] = (uint32_t)(row * SPITCH + col) * 2;
    }
    #pragma unroll
    for (int p = 0; p < 2; p++) {
        int row = wn * 32 + p * 16 + (mi >> 1) * 8 + rr;
        int col = (mi & 1) * 8;
        offB[p] = (uint32_t)(row * SPITCH + col) * 2;
    }

    int lr = tid >> 1, kofe = (tid & 1) * 16, kofu = (tid & 1) * 8;
    uint32_t stoff = (uint32_t)(lr * SPITCH + kofe) * 2;

    int K2 = K >> 1;
    const uint32_t* AHp = AH + (size_t)(bm + lr) * K2 + kofu;
    const uint32_t* ALp = AL + (size_t)(bm + lr) * K2 + kofu;
    const uint32_t* BHp = BH + (size_t)(bn + lr) * K2 + kofu;
    const uint32_t* BLp = BL + (size_t)(bn + lr) * K2 + kofu;

    float acc[4][4][4] = {};
    int NIT = K2 >> 4;

    {
        uint32_t d = sbase + stoff;
        cp16(d,                  AHp);     cp16(d + 16,                  AHp + 4);
        cp16(d + ARR_BYTES,      ALp);     cp16(d + ARR_BYTES + 16,      ALp + 4);
        cp16(d + 2 * ARR_BYTES,  BHp);     cp16(d + 2 * ARR_BYTES + 16,  BHp + 4);
        cp16(d + 3 * ARR_BYTES,  BLp);     cp16(d + 3 * ARR_BYTES + 16,  BLp + 4);
    }
    asm volatile("cp.async.commit_group;");

    for (int it = 0; it < NIT; it++) {
        int s = it & 1;
        if (it + 1 < NIT) {
            int k0 = (it + 1) << 4;
            uint32_t d = sbase + (s ^ 1) * STG_BYTES + stoff;
            cp16(d,                  AHp + k0);     cp16(d + 16,                  AHp + k0 + 4);
            cp16(d + ARR_BYTES,      ALp + k0);     cp16(d + ARR_BYTES + 16,      ALp + k0 + 4);
            cp16(d + 2 * ARR_BYTES,  BHp + k0);     cp16(d + 2 * ARR_BYTES + 16,  BHp + k0 + 4);
            cp16(d + 3 * ARR_BYTES,  BLp + k0);     cp16(d + 3 * ARR_BYTES + 16,  BLp + k0 + 4);
        }
        asm volatile("cp.async.commit_group;");
        asm volatile("cp.async.wait_group 1;");
        __syncthreads();

        uint32_t sb = sbase + s * STG_BYTES;
        #pragma unroll
        for (int kkb = 0; kkb < 64; kkb += 32) {
            uint32_t aH[4][4], aL[4][4];
            #pragma unroll
            for (int mt = 0; mt < 4; mt++) {
                ldsm4(aH[mt][0], aH[mt][1], aH[mt][2], aH[mt][3],
                      sb + offA[mt] + kkb);
                ldsm4(aL[mt][0], aL[mt][1], aL[mt][2], aL[mt][3],
                      sb + ARR_BYTES + offA[mt] + kkb);
            }
            #pragma unroll
            for (int p = 0; p < 2; p++) {
                uint32_t bH[4], bL[4];
                ldsm4(bH[0], bH[1], bH[2], bH[3], sb + 2 * ARR_BYTES + offB[p] + kkb);
                ldsm4(bL[0], bL[1], bL[2], bL[3], sb + 3 * ARR_BYTES + offB[p] + kkb);
                #pragma unroll
                for (int mt = 0; mt < 4; mt++) {
                    mma_bf16(acc[mt][2 * p],     aH[mt], bH);
                    mma_bf16(acc[mt][2 * p],     aH[mt], bL);
                    mma_bf16(acc[mt][2 * p],     aL[mt], bH);
                    mma_bf16(acc[mt][2 * p + 1], aH[mt], bH + 2);
                    mma_bf16(acc[mt][2 * p + 1], aH[mt], bL + 2);
                    mma_bf16(acc[mt][2 * p + 1], aL[mt], bH + 2);
                }
            }
        }
        __syncthreads();
    }

    int g = lane >> 2, tig = lane & 3;
    #pragma unroll
    for (int mt = 0; mt < 4; mt++) {
        #pragma unroll
        for (int rrv = 0; rrv < 2; rrv++) {
            int r = bm + wm * 64 + mt * 16 + g + rrv * 8;
            int bb = r >> 9;
            #pragma unroll
            for (int nt = 0; nt < 4; nt++) {
                int c = bn + wn * 32 + nt * 8 + 2 * tig;
                float v0 = acc[mt][nt][rrv * 2 + 0] + bias[c];
                float v1 = acc[mt][nt][rrv * 2 + 1] + bias[c + 1];
                size_t off = (size_t)r * N + c;
                if (EPI == 1) {
                    v0 = v0 * normcdff(v0);
                    v1 = v1 * normcdff(v1);
                    uint32_t hh, ll;
                    split2(v0, v1, hh, ll);
                    CH[off >> 1] = hh; CL[off >> 1] = ll;
                } else {
                    if (EPI == 2) {
                        v0 = res[off]     + gate[bb * MODS + c]     * v0;
                        v1 = res[off + 1] + gate[bb * MODS + c + 1] * v1;
                    }
                    *(float2*)(C + off) = make_float2(v0, v1);
                }
            }
        }
    }
}

// ============================================================
// 4) Rel-pos bias MLP
// ============================================================
__global__ void __launch_bounds__(128)
relpos_k(const float* __restrict__ rel,
         const float* __restrict__ w1, const float* __restrict__ b1,
         const float* __restrict__ w2, const float* __restrict__ b2,
         const int* __restrict__ mask) {
    __shared__ float W1[128], B1[64], W2T[64][16], B2s[16];
    int tid = threadIdx.x;
    if (tid < 128) W1[tid] = w1[tid];
    if (tid < 64)  B1[tid] = b1[tid];
    for (int i = tid; i < 1024; i += 128) {
        int j = i >> 4, t = i & 15;
        W2T[j][t] = w2[t * 64 + j];
    }
    if (tid < 16)  B2s[tid] = b2[tid];
    __syncthreads();
    int b = blockIdx.y, n = blockIdx.x;
    const float* rbase = rel + ((size_t)(b * Nseq + n) * Nseq) * 2;
    float2 r[4]; bool ok[4];
    #pragma unroll
    for (int i = 0; i < 4; i++) {
        int m = tid + 128 * i;
        r[i] = *(const float2*)(rbase + 2 * m);
        ok[i] = (mask[b * Nseq + m] != 0);
    }
    float out[4][16];
    #pragma unroll
    for (int i = 0; i < 4; i++)
        #pragma unroll
        for (int t = 0; t < 16; t++) out[i][t] = B2s[t];
    #pragma unroll 8
    for (int j = 0; j < 64; j++) {
        float w1x = W1[2 * j], w1y = W1[2 * j + 1], bb = B1[j];
        float hj[4];
        #pragma unroll
        for (int i = 0; i < 4; i++)
            hj[i] = fmaxf(fmaf(w1x, r[i].x, fmaf(w1y, r[i].y, bb)), 0.0f);
        float4 w0 = *(const float4*)&W2T[j][0];
        float4 w4 = *(const float4*)&W2T[j][4];
        float4 w8 = *(const float4*)&W2T[j][8];
        float4 wc = *(const float4*)&W2T[j][12];
        float wv[16] = {w0.x, w0.y, w0.z, w0.w, w4.x, w4.y, w4.z, w4.w,
                        w8.x, w8.y, w8.z, w8.w, wc.x, wc.y, wc.z, wc.w};
        #pragma unroll
        for (int i = 0; i < 4; i++)
            #pragma unroll
            for (int t = 0; t < 16; t++)
                out[i][t] = fmaf(wv[t], hj[i], out[i][t]);
    }
    #pragma unroll
    for (int t = 0; t < 16; t++) {
        #pragma unroll
        for (int i = 0; i < 4; i++) {
            int m = tid + 128 * i;
            size_t idx = (((size_t)(b * Hh + t) * Nseq) + n) * Nseq + m;
            g_bias[idx] = ok[i] ? out[i][t] : -INFINITY;
        }
    }
}

// ============================================================
// 5) Fused flash attention: S = 0.125*QK^T + bias, online
//    softmax, O = P V. P stays in registers. 64 q-rows/block,
//    4 warps, 8 key tiles of 64. Emits attn hi/lo planes.
//    Dynamic smem layout (bytes):
//      QH 0, QL 9216, KH 18432, KL 27648, VtH 36864, VtL 46080
// ============================================================
#define FL_SMEM 55296

__global__ void __launch_bounds__(128)
flash_k() {
    extern __shared__ __align__(16) char fsm[];
    __nv_bfloat16 (*QH)[72]  = (__nv_bfloat16(*)[72])(fsm);
    __nv_bfloat16 (*QL)[72]  = (__nv_bfloat16(*)[72])(fsm + 9216);
    __nv_bfloat16 (*KH)[72]  = (__nv_bfloat16(*)[72])(fsm + 18432);
    __nv_bfloat16 (*KL)[72]  = (__nv_bfloat16(*)[72])(fsm + 27648);
    __nv_bfloat16 (*VtH)[72] = (__nv_bfloat16(*)[72])(fsm + 36864);
    __nv_bfloat16 (*VtL)[72] = (__nv_bfloat16(*)[72])(fsm + 46080);

    int bh = blockIdx.y, b = bh >> 4, h = bh & 15;
    int n0 = blockIdx.x * 64;
    int tid = threadIdx.x;
    int warp = tid >> 5, lane = tid & 31;
    int g = lane >> 2, tig = lane & 3;
    int srow = tid >> 1, kof = (tid & 1) * 32;
    int dcol = tid & 63, mh = (tid >> 6) * 32;

    // ---- stage Q once ----
    {
        const float* qb = g_qkv + (size_t)(b * Nseq + n0 + srow) * 3072 + h * 64 + kof;
        #pragma unroll
        for (int q = 0; q < 8; q++) {
            float4 v = ((const float4*)qb)[q];
            uint32_t h0, l0, h1, l1;
            split2(v.x, v.y, h0, l0);
            split2(v.z, v.w, h1, l1);
            *(uint32_t*)&QH[srow][kof + q * 4]     = h0;
            *(uint32_t*)&QH[srow][kof + q * 4 + 2] = h1;
            *(uint32_t*)&QL[srow][kof + q * 4]     = l0;
            *(uint32_t*)&QL[srow][kof + q * 4 + 2] = l1;
        }
    }

    float o[8][4] = {};
    float s[8][4];
    float mrun0 = -INFINITY, mrun1 = -INFINITY;
    float lrun0 = 0.0f, lrun1 = 0.0f;
    int row0 = warp * 16 + g;

    for (int m0 = 0; m0 < Nseq; m0 += 64) {
        __syncthreads();   // protect K/V smem from previous iteration's MMAs
        // ---- stage K tile ----
        {
            const float* kb = g_qkv + (size_t)(b * Nseq + m0 + srow) * 3072 + 1024 + h * 64 + kof;
            #pragma unroll
            for (int q = 0; q < 8; q++) {
                float4 w = ((const float4*)kb)[q];
                uint32_t h0, l0, h1, l1;
                split2(w.x, w.y, h0, l0);
                split2(w.z, w.w, h1, l1);
                *(uint32_t*)&KH[srow][kof + q * 4]     = h0;
                *(uint32_t*)&KH[srow][kof + q * 4 + 2] = h1;
                *(uint32_t*)&KL[srow][kof + q * 4]     = l0;
                *(uint32_t*)&KL[srow][kof + q * 4 + 2] = l1;
            }
        }
        // ---- stage V transposed (direct gmem; coalesced across dcol) ----
        {
            const float* vb = g_qkv + (size_t)(b * Nseq + m0 + mh) * 3072 + 2048 + h * 64 + dcol;
            float tv[32];
            #pragma unroll
            for (int j = 0; j < 32; j++) tv[j] = vb[(size_t)j * 3072];
            #pragma unroll
            for (int e = 0; e < 16; e++) {
                uint32_t hh, ll;
                split2(tv[2 * e], tv[2 * e + 1], hh, ll);
                *(uint32_t*)&VtH[dcol][mh + 2 * e] = hh;
                *(uint32_t*)&VtL[dcol][mh + 2 * e] = ll;
            }
        }
        __syncthreads();

        // ---- S = Q K^T (3-MMA hi/lo) ----
        #pragma unroll
        for (int nt = 0; nt < 8; nt++) { s[nt][0] = 0; s[nt][1] = 0; s[nt][2] = 0; s[nt][3] = 0; }
        #pragma unroll
        for (int kk = 0; kk < 64; kk += 16) {
            uint32_t aH[4], aL[4];
            aH[0] = *(uint32_t*)&QH[row0][kk + 2 * tig];
            aH[1] = *(uint32_t*)&QH[row0 + 8][kk + 2 * tig];
            aH[2] = *(uint32_t*)&QH[row0][kk + 2 * tig + 8];
            aH[3] = *(uint32_t*)&QH[row0 + 8][kk + 2 * tig + 8];
            aL[0] = *(uint32_t*)&QL[row0][kk + 2 * tig];
            aL[1] = *(uint32_t*)&QL[row0 + 8][kk + 2 * tig];
            aL[2] = *(uint32_t*)&QL[row0][kk + 2 * tig + 8];
            aL[3] = *(uint32_t*)&QL[row0 + 8][kk + 2 * tig + 8];
            #pragma unroll
            for (int nt = 0; nt < 8; nt++) {
                int c0 = nt * 8 + g;
                uint32_t bH[2], bL[2];
                bH[0] = *(uint32_t*)&KH[c0][kk + 2 * tig];
                bH[1] = *(uint32_t*)&KH[c0][kk + 2 * tig + 8];
                bL[0] = *(uint32_t*)&KL[c0][kk + 2 * tig];
                bL[1] = *(uint32_t*)&KL[c0][kk + 2 * tig + 8];
                mma_bf16(s[nt], aH, bH);
                mma_bf16(s[nt], aH, bL);
                mma_bf16(s[nt], aL, bH);
            }
        }

        // ---- bias + online softmax ----
        float rmax0 = -INFINITY, rmax1 = -INFINITY;
        #pragma unroll
        for (int nt = 0; nt < 8; nt++) {
            size_t i0 = ((size_t)bh * Nseq + (n0 + row0)) * Nseq + m0 + nt * 8 + 2 * tig;
            float2 bv0 = *(const float2*)&g_bias[i0];
            float2 bv1 = *(const float2*)&g_bias[i0 + 8 * Nseq];
            s[nt][0] = fmaf(s[nt][0], 0.125f, bv0.x);
            s[nt][1] = fmaf(s[nt][1], 0.125f, bv0.y);
            s[nt][2] = fmaf(s[nt][2], 0.125f, bv1.x);
            s[nt][3] = fmaf(s[nt][3], 0.125f, bv1.y);
            rmax0 = fmaxf(rmax0, fmaxf(s[nt][0], s[nt][1]));
            rmax1 = fmaxf(rmax1, fmaxf(s[nt][2], s[nt][3]));
        }
        rmax0 = fmaxf(rmax0, __shfl_xor_sync(0xffffffff, rmax0, 1));
        rmax0 = fmaxf(rmax0, __shfl_xor_sync(0xffffffff, rmax0, 2));
        rmax1 = fmaxf(rmax1, __shfl_xor_sync(0xffffffff, rmax1, 1));
        rmax1 = fmaxf(rmax1, __shfl_xor_sync(0xffffffff, rmax1, 2));
        float nm0 = fmaxf(mrun0, rmax0), nm1 = fmaxf(mrun1, rmax1);
        float sc0 = __expf(fminf(mrun0 - nm0, 0.0f));   // fminf kills -inf - -inf NaN
        float sc1 = __expf(fminf(mrun1 - nm1, 0.0f));
        mrun0 = nm0; mrun1 = nm1;
        float ssum0 = 0.0f, ssum1 = 0.0f;
        #pragma unroll
        for (int nt = 0; nt < 8; nt++) {
            s[nt][0] = __expf(fminf(s[nt][0] - nm0, 0.0f));
            s[nt][1] = __expf(fminf(s[nt][1] - nm0, 0.0f));
            s[nt][2] = __expf(fminf(s[nt][2] - nm1, 0.0f));
            s[nt][3] = __expf(fminf(s[nt][3] - nm1, 0.0f));
            ssum0 += s[nt][0] + s[nt][1];
            ssum1 += s[nt][2] + s[nt][3];
            o[nt][0] *= sc0; o[nt][1] *= sc0;
            o[nt][2] *= sc1; o[nt][3] *= sc1;
        }
        ssum0 += __shfl_xor_sync(0xffffffff, ssum0, 1);
        ssum0 += __shfl_xor_sync(0xffffffff, ssum0, 2);
        ssum1 += __shfl_xor_sync(0xffffffff, ssum1, 1);
        ssum1 += __shfl_xor_sync(0xffffffff, ssum1, 2);
        lrun0 = lrun0 * sc0 + ssum0;
        lrun1 = lrun1 * sc1 + ssum1;

        // ---- O += P V : P fragments straight from registers ----
        #pragma unroll
        for (int kk = 0; kk < 64; kk += 16) {
            int t0 = kk >> 3;
            uint32_t aPH[4], aPL[4];
            split2(s[t0][0],     s[t0][1],     aPH[0], aPL[0]);
            split2(s[t0][2],     s[t0][3],     aPH[1], aPL[1]);
            split2(s[t0 + 1][0], s[t0 + 1][1], aPH[2], aPL[2]);
            split2(s[t0 + 1][2], s[t0 + 1][3], aPH[3], aPL[3]);
            #pragma unroll
            for (int nt = 0; nt < 8; nt++) {
                int c0 = nt * 8 + g;
                uint32_t bH[2], bL[2];
                bH[0] = *(uint32_t*)&VtH[c0][kk + 2 * tig];
                bH[1] = *(uint32_t*)&VtH[c0][kk + 2 * tig + 8];
                bL[0] = *(uint32_t*)&VtL[c0][kk + 2 * tig];
                bL[1] = *(uint32_t*)&VtL[c0][kk + 2 * tig + 8];
                mma_bf16(o[nt], aPH, bH);
                mma_bf16(o[nt], aPH, bL);
                mma_bf16(o[nt], aPL, bH);
            }
        }
    }

    // ---- normalize + write attn hi/lo planes ----
    float inv0 = 1.0f / lrun0, inv1 = 1.0f / lrun1;
    #pragma unroll
    for (int nt = 0; nt < 8; nt++) {
        int d = nt * 8 + 2 * tig;
        uint32_t hh, ll;
        split2(o[nt][0] * inv0, o[nt][1] * inv0, hh, ll);
        size_t off0 = ((size_t)(b * Nseq + n0 + row0) * Dd + h * 64 + d) >> 1;
        g_attnH[off0] = hh; g_attnL[off0] = ll;
        split2(o[nt][2] * inv1, o[nt][3] * inv1, hh, ll);
        size_t off1 = ((size_t)(b * Nseq + n0 + row0 + 8) * Dd + h * 64 + d) >> 1;
        g_attnH[off1] = hh; g_attnL[off1] = ll;
    }
}

// ============================================================
// host-side launcher
// ============================================================
extern "C" void kernel_launch(void* const* d_in, const int* in_sizes, int n_in,
                              void* d_out, int out_size) {
    const float* x      = (const float*)d_in[0];
    const float* t_emb  = (const float*)d_in[1];
    const float* rel    = (const float*)d_in[2];
    const int*   mask   = (const int*)d_in[3];
    const float* w_ada  = (const float*)d_in[4];
    const float* b_ada  = (const float*)d_in[5];
    const float* g1     = (const float*)d_in[6];
    const float* beta1  = (const float*)d_in[7];
    const float* g2     = (const float*)d_in[8];
    const float* beta2  = (const float*)d_in[9];
    const float* w_qkv  = (const float*)d_in[10];
    const float* b_qkv  = (const float*)d_in[11];
    const float* w_proj = (const float*)d_in[12];
    const float* b_proj = (const float*)d_in[13];
    const float* w_rp1  = (const float*)d_in[14];
    const float* b_rp1  = (const float*)d_in[15];
    const float* w_rp2  = (const float*)d_in[16];
    const float* b_rp2  = (const float*)d_in[17];
    const float* w_fc1  = (const float*)d_in[18];
    const float* b_fc1  = (const float*)d_in[19];
    const float* w_fc2  = (const float*)d_in[20];
    const float* b_fc2  = (const float*)d_in[21];
    float* out = (float*)d_out;

    void *p_mod, *p_qkv, *p_x1;
    void *p_xnH, *p_xnL, *p_attnH, *p_attnL, *p_hH, *p_hL;
    void *p_wqkvH, *p_wqkvL, *p_wprojH, *p_wprojL, *p_wfc1H, *p_wfc1L, *p_wfc2H, *p_wfc2L;
    cudaGetSymbolAddress(&p_mod,  g_mod);
    cudaGetSymbolAddress(&p_qkv,  g_qkv);
    cudaGetSymbolAddress(&p_x1,   g_x1);
    cudaGetSymbolAddress(&p_xnH,  g_xnH);
    cudaGetSymbolAddress(&p_xnL,  g_xnL);
    cudaGetSymbolAddress(&p_attnH, g_attnH);
    cudaGetSymbolAddress(&p_attnL, g_attnL);
    cudaGetSymbolAddress(&p_hH,   g_hH);
    cudaGetSymbolAddress(&p_hL,   g_hL);
    cudaGetSymbolAddress(&p_wqkvH, g_wqkvH);
    cudaGetSymbolAddress(&p_wqkvL, g_wqkvL);
    cudaGetSymbolAddress(&p_wprojH, g_wprojH);
    cudaGetSymbolAddress(&p_wprojL, g_wprojL);
    cudaGetSymbolAddress(&p_wfc1H, g_wfc1H);
    cudaGetSymbolAddress(&p_wfc1L, g_wfc1L);
    cudaGetSymbolAddress(&p_wfc2H, g_wfc2H);
    cudaGetSymbolAddress(&p_wfc2L, g_wfc2L);
    float* modf = (float*)p_mod;

    cudaFuncSetAttribute(gemm_tc<0>, cudaFuncAttributeMaxDynamicSharedMemorySize, SMEM_DYN);
    cudaFuncSetAttribute(gemm_tc<1>, cudaFuncAttributeMaxDynamicSharedMemorySize, SMEM_DYN);
    cudaFuncSetAttribute(gemm_tc<2>, cudaFuncAttributeMaxDynamicSharedMemorySize, SMEM_DYN);
    cudaFuncSetAttribute(flash_k,    cudaFuncAttributeMaxDynamicSharedMemorySize, FL_SMEM);

    // 0. weight hi/lo planes (float4 vectorized)
    cvtw_k<<<(3 * Dd * Dd / 4) / 256, 256>>>((const float4*)w_qkv, (uint2*)p_wqkvH, (uint2*)p_wqkvL);
    cvtw_k<<<(Dd * Dd / 4) / 256, 256>>>((const float4*)w_proj, (uint2*)p_wprojH, (uint2*)p_wprojL);
    cvtw_k<<<(HIDd * Dd / 4) / 256, 256>>>((const float4*)w_fc1, (uint2*)p_wfc1H, (uint2*)p_wfc1L);
    cvtw_k<<<(Dd * HIDd / 4) / 256, 256>>>((const float4*)w_fc2, (uint2*)p_wfc2H, (uint2*)p_wfc2L);
    // 1. adaLN modulation
    adaln_k<<<dim3(768, 4), 256>>>(t_emb, w_ada, b_ada);
    // 2. LN1 + modulate -> xn planes
    ln_mod_k<<<MM, 256>>>(x, g1, beta1, 0, Dd,
                          (__nv_bfloat16*)p_xnH, (__nv_bfloat16*)p_xnL);
    // 3. QKV projection
    gemm_tc<0><<<dim3(3072 / 128, MM / 128), 256, SMEM_DYN>>>(
        (const uint32_t*)p_xnH, (const uint32_t*)p_xnL,
        (const uint32_t*)p_wqkvH, (const uint32_t*)p_wqkvL,
        b_qkv, nullptr, nullptr, (float*)p_qkv, nullptr, nullptr, MM, 3072, Dd);
    // 4. rel-pos bias
    relpos_k<<<dim3(Nseq, Bb), 128>>>(rel, w_rp1, b_rp1, w_rp2, b_rp2, mask);
    // 5-7. fused flash attention -> attn planes
    flash_k<<<dim3(8, Bb * Hh), 128, FL_SMEM>>>();
    // 8. proj + residual gate_s
    gemm_tc<2><<<dim3(1024 / 128, MM / 128), 256, SMEM_DYN>>>(
        (const uint32_t*)p_attnH, (const uint32_t*)p_attnL,
        (const uint32_t*)p_wprojH, (const uint32_t*)p_wprojL,
        b_proj, x, modf + 2 * Dd, (float*)p_x1, nullptr, nullptr, MM, Dd, Dd);
    // 9. LN2 + modulate -> xn planes
    ln_mod_k<<<MM, 256>>>((const float*)p_x1, g2, beta2, 3 * Dd, 4 * Dd,
                          (__nv_bfloat16*)p_xnH, (__nv_bfloat16*)p_xnL);
    // 10. fc1 + GELU -> hidden planes
    gemm_tc<1><<<dim3(HIDd / 128, MM / 128), 256, SMEM_DYN>>>(
        (const uint32_t*)p_xnH, (const uint32_t*)p_xnL,
        (const uint32_t*)p_wfc1H, (const uint32_t*)p_wfc1L,
        b_fc1, nullptr, nullptr, nullptr, (uint32_t*)p_hH, (uint32_t*)p_hL, MM, HIDd, Dd);
    // 11. fc2 + residual gate_m -> final output
    gemm_tc<2><<<dim3(1024 / 128, MM / 128), 256, SMEM_DYN>>>(
        (const uint32_t*)p_hH, (const uint32_t*)p_hL,
        (const uint32_t*)p_wfc2H, (const uint32_t*)p_wfc2L,
        b_fc2, (const float*)p_x1, modf + 5 * Dd, out, nullptr, nullptr, MM, Dd, HIDd);
}